// round 9
// baseline (speedup 1.0000x reference)
#include <cuda_runtime.h>
#include <cuda_fp16.h>
#include <cstdint>

#define NB    16
#define NDIM  128
#define NPTS  16384
#define NJ    16
#define NR    8
#define KT    32                     // K-tile depth
#define ROWPAD 40                    // padded smem row (elements)
#define TILE_B (128 * ROWPAD * 2)    // 10240 bytes per fp16 tile
#define WSCALE 16384.0f
#define WINV   (1.0f / 16384.0f)

typedef __half hf;

// ---------------- device scratch ----------------
__device__ __align__(16) float g_xhatT[NB * 128 * 128];      // [b][l][i]  1 MB
__device__ __align__(16) float g_y    [NB * 128 * 128];      // [(b,o)][k] 1 MB (scaled 2^14)
__device__ __align__(16) hf g_xhT_h[NB * 128 * 128], g_xhT_l[NB * 128 * 128];
__device__ __align__(16) hf g_Wt_h [NJ * 128 * 128], g_Wt_l [NJ * 128 * 128];   // [j][o][i] (x 2^14)
__device__ __align__(16) hf g_Hk_h [128 * NJ * 128], g_Hk_l [128 * NJ * 128];   // [k][(j,l)]
__device__ __align__(16) hf g_z_h  [2048 * 2048],    g_z_l  [2048 * 2048];      // [(b,o)][(j,l)] scaled
__device__ __align__(16) hf g_y_h  [2048 * 128];                                 // descaled fp16
__device__ __align__(16) hf g_wbT_h[128 * NPTS];                                 // [l][x]
__device__ __align__(16) hf g_bs_h [NPTS * 128];                                 // [x][k]

// ---------------- helpers ----------------
__device__ __forceinline__ uint32_t smem_u32(const void* p) {
    uint32_t a;
    asm("{ .reg .u64 t; cvta.to.shared.u64 t, %1; cvt.u32.u64 %0, t; }" : "=r"(a) : "l"(p));
    return a;
}
__device__ __forceinline__ void cp16(uint32_t dst, const void* src) {
    asm volatile("cp.async.cg.shared.global [%0], [%1], 16;" :: "r"(dst), "l"(src));
}
__device__ __forceinline__ void cp_commit() {
    asm volatile("cp.async.commit_group;" ::: "memory");
}
template <int N>
__device__ __forceinline__ void cp_wait() {
    asm volatile("cp.async.wait_group %0;" :: "n"(N) : "memory");
}
__device__ __forceinline__ void ldmx4(uint32_t* r, uint32_t addr) {
    asm volatile("ldmatrix.sync.aligned.m8n8.x4.shared.b16 {%0,%1,%2,%3}, [%4];"
                 : "=r"(r[0]), "=r"(r[1]), "=r"(r[2]), "=r"(r[3]) : "r"(addr));
}
__device__ __forceinline__ void mma_f16(float* c, const uint32_t* a, const uint32_t* b) {
    asm volatile("mma.sync.aligned.m16n8k16.row.col.f32.f16.f16.f32 "
                 "{%0,%1,%2,%3}, {%4,%5,%6,%7}, {%8,%9}, {%0,%1,%2,%3};"
                 : "+f"(c[0]), "+f"(c[1]), "+f"(c[2]), "+f"(c[3])
                 : "r"(a[0]), "r"(a[1]), "r"(a[2]), "r"(a[3]), "r"(b[0]), "r"(b[1]));
}
// fp32x4 -> fp16x2 pair (hi only)
__device__ __forceinline__ uint2 cvt_h4(float4 v) {
    __half2 h0 = __floats2half2_rn(v.x, v.y);
    __half2 h1 = __floats2half2_rn(v.z, v.w);
    return make_uint2(*(uint32_t*)&h0, *(uint32_t*)&h1);
}
// fp32x4 -> hi + lo residual pairs
__device__ __forceinline__ void cvt_hl4(float4 v, uint2& hi, uint2& lo) {
    __half2 h0 = __floats2half2_rn(v.x, v.y);
    __half2 h1 = __floats2half2_rn(v.z, v.w);
    float rx = v.x - __low2float(h0),  ry = v.y - __high2float(h0);
    float rz = v.z - __low2float(h1),  rw = v.w - __high2float(h1);
    __half2 l0 = __floats2half2_rn(rx, ry);
    __half2 l1 = __floats2half2_rn(rz, rw);
    hi = make_uint2(*(uint32_t*)&h0, *(uint32_t*)&h1);
    lo = make_uint2(*(uint32_t*)&l0, *(uint32_t*)&l1);
}
__device__ __forceinline__ void split1(float v, hf& h, hf& l) {
    h = __float2half_rn(v);
    l = __float2half_rn(v - __half2float(h));
}
__device__ __forceinline__ void split2(float a, float b, uint32_t& hw, uint32_t& lw) {
    __half2 h = __floats2half2_rn(a, b);
    float ra = a - __low2float(h), rb = b - __high2float(h);
    __half2 l = __floats2half2_rn(ra, rb);
    hw = *(uint32_t*)&h;
    lw = *(uint32_t*)&l;
}

// ---------------- tile slot layout per TERMS ----------------
// TERMS==1: [Ah, Bh]            NT=2
// TERMS==3: [Ah, Al, Bh, Bl]    NT=4
template <int TERMS> struct Slots {
    static constexpr int SAh = 0;
    static constexpr int SAl = 1;                       // valid TERMS>=2
    static constexpr int SBh = (TERMS == 1) ? 1 : 2;
    static constexpr int SBl = 3;                       // valid TERMS==3
    static constexpr int NT  = (TERMS == 1) ? 2 : (TERMS == 2) ? 3 : 4;
    static constexpr int BUF = NT * TILE_B;
};

// ---------------- compute one 32-deep K tile ----------------
template <int TERMS>
__device__ __forceinline__ void compute_kt(uint32_t bb, float acc[16][4],
                                           int a_off, int b_off, int wr, int wc) {
    using S = Slots<TERMS>;
#pragma unroll
    for (int ks = 0; ks < 2; ++ks) {
        const uint32_t koff = ks * 32;
        uint32_t bh[4][2], bl[4][2];
#pragma unroll
        for (int n2 = 0; n2 < 2; ++n2) {
            const uint32_t nbase = (wc * 32 + n2 * 16) * 80 + koff + b_off;
            uint32_t r4[4];
            ldmx4(r4, bb + S::SBh * TILE_B + nbase);
            bh[n2 * 2][0] = r4[0]; bh[n2 * 2][1] = r4[1];
            bh[n2 * 2 + 1][0] = r4[2]; bh[n2 * 2 + 1][1] = r4[3];
            if (TERMS == 3) {
                ldmx4(r4, bb + S::SBl * TILE_B + nbase);
                bl[n2 * 2][0] = r4[0]; bl[n2 * 2][1] = r4[1];
                bl[n2 * 2 + 1][0] = r4[2]; bl[n2 * 2 + 1][1] = r4[3];
            }
        }
#pragma unroll
        for (int mi = 0; mi < 4; ++mi) {
            const uint32_t mbase = (wr * 64 + mi * 16) * 80 + koff + a_off;
            uint32_t ah[4], al[4];
            ldmx4(ah, bb + S::SAh * TILE_B + mbase);
            if (TERMS >= 2) ldmx4(al, bb + S::SAl * TILE_B + mbase);
#pragma unroll
            for (int ni = 0; ni < 4; ++ni) {
                mma_f16(acc[mi * 4 + ni], ah, bh[ni]);
                if (TERMS >= 2) mma_f16(acc[mi * 4 + ni], al, bh[ni]);
                if (TERMS == 3) mma_f16(acc[mi * 4 + ni], ah, bl[ni]);
            }
        }
    }
}

// issue cp.async for one fp16 tile (2x16B chunks/thread; 64B data per 80B row)
__device__ __forceinline__ void issue_tile(uint32_t bb, int tile, const hf* base,
                                           int ld, int k0, int t) {
    int row = t >> 2, q = t & 3;
    cp16(bb + tile * TILE_B + row * 80 + q * 16, base + (size_t)row * ld + k0 + q * 8);
    row = (t + 256) >> 2; q = (t + 256) & 3;
    cp16(bb + tile * TILE_B + row * 80 + q * 16, base + (size_t)row * ld + k0 + q * 8);
}

// ---------------- pre-split fp16 core (TERMS = 1 or 3) ----------------
template <int TERMS>
__device__ __forceinline__ void mm_f16_core(const hf* __restrict__ Ah,
                                            const hf* __restrict__ Al, int lda,
                                            const hf* __restrict__ Bh,
                                            const hf* __restrict__ Bl, int ldb,
                                            int ktiles, float acc[16][4]) {
    using S = Slots<TERMS>;
    extern __shared__ __align__(128) char dsm[];
    const int t = threadIdx.x, lane = t & 31, w = t >> 5;
    const int wr = w >> 2, wc = w & 3;
    const uint32_t sb = smem_u32(dsm);
    const int a_off = ((lane & 7) + ((lane >> 3) & 1) * 8) * 80 + ((lane >> 4) & 1) * 16;
    const int b_off = ((lane & 7) + ((lane >> 4) & 1) * 8) * 80 + ((lane >> 3) & 1) * 16;

#pragma unroll
    for (int i = 0; i < 16; ++i)
#pragma unroll
        for (int j = 0; j < 4; ++j) acc[i][j] = 0.0f;

    issue_tile(sb, S::SAh, Ah, lda, 0, t);
    if (TERMS >= 2) issue_tile(sb, S::SAl, Al, lda, 0, t);
    issue_tile(sb, S::SBh, Bh, ldb, 0, t);
    if (TERMS == 3) issue_tile(sb, S::SBl, Bl, ldb, 0, t);
    cp_commit();

    int cur = 0;
    for (int kt = 0; kt < ktiles; ++kt) {
        const bool more = (kt + 1 < ktiles);
        if (more) {
            const uint32_t nb = sb + (cur ^ 1) * S::BUF;
            const int k0 = (kt + 1) * KT;
            issue_tile(nb, S::SAh, Ah, lda, k0, t);
            if (TERMS >= 2) issue_tile(nb, S::SAl, Al, lda, k0, t);
            issue_tile(nb, S::SBh, Bh, ldb, k0, t);
            if (TERMS == 3) issue_tile(nb, S::SBl, Bl, ldb, k0, t);
            cp_commit();
            cp_wait<1>();
        } else {
            cp_wait<0>();
        }
        __syncthreads();
        compute_kt<TERMS>(sb + cur * S::BUF, acc, a_off, b_off, wr, wc);
        __syncthreads();
        cur ^= 1;
    }
}

// ---------------- stage-A core: single term, A fp32 in-kernel cvt ----------------
__device__ __forceinline__ void mm_a_core(const float* __restrict__ A, int lda,
                                          const hf* __restrict__ Bh, int ldb,
                                          int ktiles, float acc[16][4]) {
    using S = Slots<1>;
    extern __shared__ __align__(128) char dsm[];
    const int t = threadIdx.x, lane = t & 31, w = t >> 5;
    const int wr = w >> 2, wc = w & 3;
    const uint32_t sb = smem_u32(dsm);
    const int a_off = ((lane & 7) + ((lane >> 3) & 1) * 8) * 80 + ((lane >> 4) & 1) * 16;
    const int b_off = ((lane & 7) + ((lane >> 4) & 1) * 8) * 80 + ((lane >> 3) & 1) * 16;

#pragma unroll
    for (int i = 0; i < 16; ++i)
#pragma unroll
        for (int j = 0; j < 4; ++j) acc[i][j] = 0.0f;

    float4 av[4];
    issue_tile(sb, S::SBh, Bh, ldb, 0, t);
    cp_commit();
#pragma unroll
    for (int i = 0; i < 4; ++i) {
        const int idx = t + 256 * i, r = idx >> 3, c4 = (idx & 7) << 2;
        av[i] = *(const float4*)&A[(size_t)r * lda + c4];
    }
#pragma unroll
    for (int i = 0; i < 4; ++i) {
        const int idx = t + 256 * i, r = idx >> 3, c4 = (idx & 7) << 2;
        *(uint2*)(dsm + S::SAh * TILE_B + r * 80 + c4 * 2) = cvt_h4(av[i]);
    }

    int cur = 0;
    for (int kt = 0; kt < ktiles; ++kt) {
        const bool more = (kt + 1 < ktiles);
        if (more) {
#pragma unroll
            for (int i = 0; i < 4; ++i) {
                const int idx = t + 256 * i, r = idx >> 3, c4 = (idx & 7) << 2;
                av[i] = *(const float4*)&A[(size_t)r * lda + (kt + 1) * KT + c4];
            }
            issue_tile(sb + (cur ^ 1) * S::BUF, S::SBh, Bh, ldb, (kt + 1) * KT, t);
            cp_commit();
            cp_wait<1>();
        } else {
            cp_wait<0>();
        }
        __syncthreads();
        compute_kt<1>(sb + cur * S::BUF, acc, a_off, b_off, wr, wc);
        __syncthreads();
        if (more) {
#pragma unroll
            for (int i = 0; i < 4; ++i) {
                const int idx = t + 256 * i, r = idx >> 3, c4 = (idx & 7) << 2;
                *(uint2*)(dsm + (cur ^ 1) * S::BUF + S::SAh * TILE_B + r * 80 + c4 * 2) =
                    cvt_h4(av[i]);
            }
        }
        cur ^= 1;
    }
}

// ---------------- prep kernels ----------------
__global__ void zero_kernel() {
    int i = blockIdx.x * 256 + threadIdx.x;   // 262144 each
    g_xhatT[i] = 0.0f;
    g_y[i]     = 0.0f;
}

__global__ void __launch_bounds__(256) ht_kernel(const float* __restrict__ Aop,
                                                 const float* __restrict__ Bop,
                                                 const float* __restrict__ Dout,
                                                 const float* __restrict__ Din,
                                                 const float* __restrict__ product) {
    int j = blockIdx.x;
    int t = threadIdx.x;
    __shared__ float Aj[NR * 64];
    __shared__ float Bj[NR * 64];
    __shared__ float Qs[64 * 64];
    for (int i = t; i < NR * 64; i += 256) {
        Aj[i] = Aop[j * (NR * 64) + i];
        Bj[i] = Bop[j * (NR * 64) + i];
    }
    __syncthreads();
#pragma unroll
    for (int s = 0; s < 16; ++s) {
        int idx = t + 256 * s;
        int m = idx >> 6, n = idx & 63;
        float q = 0.0f;
#pragma unroll
        for (int r = 0; r < NR; ++r) q += Aj[r * 64 + m] * Bj[r * 64 + n];
        Qs[idx] = q;
    }
    __syncthreads();
#pragma unroll 4
    for (int s = 0; s < 64; ++s) {
        int idx = t + 256 * s;        // 16384 = 128x128
        int k = idx >> 7, l = idx & 127;
        float h = Dout[j * 128 + k] * Din[j * 128 + l] * product[k * 128 + l];
        if (k < 64 && l < 64) h += Qs[k * 64 + l];
        hf hh, ll;
        split1(h, hh, ll);
        g_Hk_h[k * (NJ * 128) + j * 128 + l] = hh;
        g_Hk_l[k * (NJ * 128) + j * 128 + l] = ll;
    }
}

__global__ void wt_kernel(const float* __restrict__ w) {
    int id = blockIdx.x * 256 + threadIdx.x;   // 262144
    int ii = id & 127;
    int o  = (id >> 7) & 127;
    int j  = id >> 14;
    hf h, l;
    split1(w[(ii * 128 + o) * NJ + j] * WSCALE, h, l);
    g_Wt_h[id] = h;
    g_Wt_l[id] = l;
}

// wbases[NPTS][128] -> wbT_h [128][NPTS] (fp16, single)
__global__ void __launch_bounds__(256) twb_kernel(const float* __restrict__ wb) {
    __shared__ float tile[32][33];
    int xb = blockIdx.x * 32, kb = blockIdx.y * 32;
    int tx = threadIdx.x & 31, ty = threadIdx.x >> 5;
#pragma unroll
    for (int i = 0; i < 32; i += 8)
        tile[ty + i][tx] = wb[(size_t)(xb + ty + i) * 128 + kb + tx];
    __syncthreads();
#pragma unroll
    for (int i = 0; i < 32; i += 8)
        g_wbT_h[(size_t)(kb + ty + i) * NPTS + xb + tx] = __float2half_rn(tile[tx][ty + i]);
}

// bases elementwise -> fp16 (single)
__global__ void __launch_bounds__(256) tbs_kernel(const float* __restrict__ bases) {
    int i4 = blockIdx.x * 256 + threadIdx.x;   // 524288 float4s
    float4 v = ((const float4*)bases)[i4];
    *(uint2*)&g_bs_h[(size_t)i4 * 4] = cvt_h4(v);
}

// fp32 -> hi/lo split for xhatT (SEL=0); y -> descaled fp16 hi only (SEL=1)
template <int SEL>
__global__ void __launch_bounds__(256) cvt_big_kernel() {
    int i4 = blockIdx.x * 256 + threadIdx.x;   // 65536 float4s
    if (SEL == 0) {
        float4 v = ((const float4*)g_xhatT)[i4];
        uint2 hi, lo;
        cvt_hl4(v, hi, lo);
        *(uint2*)&g_xhT_h[(size_t)i4 * 4] = hi;
        *(uint2*)&g_xhT_l[(size_t)i4 * 4] = lo;
    } else {
        float4 v = ((const float4*)g_y)[i4];
        v.x *= WINV; v.y *= WINV; v.z *= WINV; v.w *= WINV;
        *(uint2*)&g_y_h[(size_t)i4 * 4] = cvt_h4(v);
    }
}

// ---------------- GEMM stage kernels ----------------
// stage A: xhatT[b][l][i] += x[(b,i),:] @ wbT  (16 b-blocks x 16 K-splits, 1-term)
__global__ void __launch_bounds__(256, 2) k_mm_a(const float* __restrict__ x) {
    const int b  = blockIdx.x;
    const int ks = blockIdx.y;                 // 16 splits x 1024 K
    float acc[16][4];
    mm_a_core(x + (size_t)(b * 128) * NPTS + ks * 1024, NPTS,
              g_wbT_h + ks * 1024, NPTS, 32, acc);
    const int lane = threadIdx.x & 31, w = threadIdx.x >> 5;
    const int wr = w >> 2, wc = w & 3;
    float* dst = g_xhatT + (size_t)b * 16384;
#pragma unroll
    for (int mi = 0; mi < 4; ++mi)
#pragma unroll
        for (int ni = 0; ni < 4; ++ni) {
            const int row = wr * 64 + mi * 16 + (lane >> 2);   // i
            const int col = wc * 32 + ni * 8 + (lane & 3) * 2; // l
            const float* a = acc[mi * 4 + ni];
            atomicAdd(&dst[(col + 0) * 128 + row],     a[0]);
            atomicAdd(&dst[(col + 1) * 128 + row],     a[1]);
            atomicAdd(&dst[(col + 0) * 128 + row + 8], a[2]);
            atomicAdd(&dst[(col + 1) * 128 + row + 8], a[3]);
        }
}

// stage Z: z[(b,o)][(j,l)] = Wt'[j] @ xhatT[b]^T (3-term), stored split fp16
__global__ void __launch_bounds__(256) k_mm_z() {
    const int b = blockIdx.x >> 4, j = blockIdx.x & 15;
    float acc[16][4];
    mm_f16_core<3>(g_Wt_h + (size_t)j * 16384, g_Wt_l + (size_t)j * 16384, 128,
                   g_xhT_h + (size_t)b * 16384, g_xhT_l + (size_t)b * 16384, 128, 4, acc);
    const int lane = threadIdx.x & 31, w = threadIdx.x >> 5;
    const int wr = w >> 2, wc = w & 3;
#pragma unroll
    for (int mi = 0; mi < 4; ++mi)
#pragma unroll
        for (int ni = 0; ni < 4; ++ni) {
            const int row = wr * 64 + mi * 16 + (lane >> 2);   // o
            const int col = wc * 32 + ni * 8 + (lane & 3) * 2; // l
            const float* a = acc[mi * 4 + ni];
            uint32_t hw, lw;
            size_t idx0 = (size_t)(b * 128 + row) * 2048 + j * 128 + col;
            split2(a[0], a[1], hw, lw);
            *(uint32_t*)&g_z_h[idx0] = hw;
            *(uint32_t*)&g_z_l[idx0] = lw;
            size_t idx1 = idx0 + (size_t)8 * 2048;
            split2(a[2], a[3], hw, lw);
            *(uint32_t*)&g_z_h[idx1] = hw;
            *(uint32_t*)&g_z_l[idx1] = lw;
        }
}

// stage Y: y[(b,o)][k] += z @ Hk (3-term; 16 row-blocks x 8 K-splits)
__global__ void __launch_bounds__(256) k_mm_y() {
    const int row0 = blockIdx.x * 128;
    const int kt0  = blockIdx.y * 8;
    float acc[16][4];
    mm_f16_core<3>(g_z_h + (size_t)row0 * 2048 + kt0 * KT,
                   g_z_l + (size_t)row0 * 2048 + kt0 * KT, 2048,
                   g_Hk_h + kt0 * KT, g_Hk_l + kt0 * KT, 2048, 8, acc);
    const int lane = threadIdx.x & 31, w = threadIdx.x >> 5;
    const int wr = w >> 2, wc = w & 3;
#pragma unroll
    for (int mi = 0; mi < 4; ++mi)
#pragma unroll
        for (int ni = 0; ni < 4; ++ni) {
            const int row = row0 + wr * 64 + mi * 16 + (lane >> 2);
            const int col = wc * 32 + ni * 8 + (lane & 3) * 2;
            const float* a = acc[mi * 4 + ni];
            atomicAdd(&g_y[(size_t)row * 128 + col],           a[0]);
            atomicAdd(&g_y[(size_t)row * 128 + col + 1],       a[1]);
            atomicAdd(&g_y[(size_t)(row + 8) * 128 + col],     a[2]);
            atomicAdd(&g_y[(size_t)(row + 8) * 128 + col + 1], a[3]);
        }
}

// stage D: out = y_h @ bases_h^T (1-term)
__global__ void __launch_bounds__(256, 2) k_mm_d(float* __restrict__ out) {
    const int row0 = blockIdx.x * 128;
    const int x0   = blockIdx.y * 128;
    float acc[16][4];
    mm_f16_core<1>(g_y_h + (size_t)row0 * 128, (const hf*)nullptr, 128,
                   g_bs_h + (size_t)x0 * 128, (const hf*)nullptr, 128, 4, acc);
    const int lane = threadIdx.x & 31, w = threadIdx.x >> 5;
    const int wr = w >> 2, wc = w & 3;
#pragma unroll
    for (int mi = 0; mi < 4; ++mi)
#pragma unroll
        for (int ni = 0; ni < 4; ++ni) {
            const int row = row0 + wr * 64 + mi * 16 + (lane >> 2);
            const int col = x0 + wc * 32 + ni * 8 + (lane & 3) * 2;
            const float* a = acc[mi * 4 + ni];
            *(float2*)&out[(size_t)row * NPTS + col]       = make_float2(a[0], a[1]);
            *(float2*)&out[(size_t)(row + 8) * NPTS + col] = make_float2(a[2], a[3]);
        }
}

// ---------------- launch ----------------
extern "C" void kernel_launch(void* const* d_in, const int* in_sizes, int n_in,
                              void* d_out, int out_size) {
    const float* x       = (const float*)d_in[0];
    const float* bases   = (const float*)d_in[1];
    const float* wbases  = (const float*)d_in[2];
    const float* product = (const float*)d_in[3];
    const float* Dout    = (const float*)d_in[4];
    const float* Din     = (const float*)d_in[5];
    const float* Aop     = (const float*)d_in[6];
    const float* Bop     = (const float*)d_in[7];
    const float* weights = (const float*)d_in[8];
    float* out = (float*)d_out;

    const int SM_1 = 2 * Slots<1>::BUF;   // 40960
    const int SM_3 = 2 * Slots<3>::BUF;   // 81920
    cudaFuncSetAttribute(k_mm_a, cudaFuncAttributeMaxDynamicSharedMemorySize, SM_1);
    cudaFuncSetAttribute(k_mm_z, cudaFuncAttributeMaxDynamicSharedMemorySize, SM_3);
    cudaFuncSetAttribute(k_mm_y, cudaFuncAttributeMaxDynamicSharedMemorySize, SM_3);
    cudaFuncSetAttribute(k_mm_d, cudaFuncAttributeMaxDynamicSharedMemorySize, SM_1);

    zero_kernel<<<1024, 256>>>();
    ht_kernel<<<NJ, 256>>>(Aop, Bop, Dout, Din, product);
    wt_kernel<<<1024, 256>>>(weights);
    twb_kernel<<<dim3(NPTS / 32, 4), 256>>>(wbases);
    tbs_kernel<<<2048, 256>>>(bases);

    k_mm_a<<<dim3(16, 16), 256, SM_1>>>(x);
    cvt_big_kernel<0><<<256, 256>>>();
    k_mm_z<<<NB * NJ, 256, SM_3>>>();
    k_mm_y<<<dim3(16, 8), 256, SM_3>>>();
    cvt_big_kernel<1><<<256, 256>>>();
    k_mm_d<<<dim3(16, 128), 256, SM_1>>>(out);
}

// round 10
// speedup vs baseline: 1.0442x; 1.0442x over previous
#include <cuda_runtime.h>
#include <cuda_fp16.h>
#include <cstdint>

#define NB    16
#define NDIM  128
#define NPTS  16384
#define NJ    16
#define NR    8
#define KT    32                     // K-tile depth
#define ROWPAD 40                    // padded smem row (elements)
#define TILE_B (128 * ROWPAD * 2)    // 10240 bytes per fp16 tile
#define WSCALE 16384.0f
#define WINV   (1.0f / 16384.0f)

typedef __half hf;

// ---------------- device scratch ----------------
__device__ __align__(16) float g_xhatT[NB * 128 * 128];      // [b][l][i]  1 MB
__device__ __align__(16) float g_y    [NB * 128 * 128];      // [(b,o)][k] 1 MB (scaled 2^14)
__device__ __align__(16) hf g_xhT_h[NB * 128 * 128], g_xhT_l[NB * 128 * 128];
__device__ __align__(16) hf g_Wt_h [NJ * 128 * 128], g_Wt_l [NJ * 128 * 128];   // [j][o][i] (x 2^14)
__device__ __align__(16) hf g_Hk_h [128 * NJ * 128], g_Hk_l [128 * NJ * 128];   // [k][(j,l)]
__device__ __align__(16) hf g_z_h  [2048 * 2048],    g_z_l  [2048 * 2048];      // [(b,o)][(j,l)] scaled
__device__ __align__(16) hf g_y_h  [2048 * 128];                                 // descaled fp16
__device__ __align__(16) hf g_wbT_h[128 * NPTS];                                 // [l][x]
__device__ __align__(16) hf g_bs_h [NPTS * 128];                                 // [x][k]

// ---------------- helpers ----------------
__device__ __forceinline__ uint32_t smem_u32(const void* p) {
    uint32_t a;
    asm("{ .reg .u64 t; cvta.to.shared.u64 t, %1; cvt.u32.u64 %0, t; }" : "=r"(a) : "l"(p));
    return a;
}
__device__ __forceinline__ void cp16(uint32_t dst, const void* src) {
    asm volatile("cp.async.cg.shared.global [%0], [%1], 16;" :: "r"(dst), "l"(src));
}
__device__ __forceinline__ void cp_commit() {
    asm volatile("cp.async.commit_group;" ::: "memory");
}
template <int N>
__device__ __forceinline__ void cp_wait() {
    asm volatile("cp.async.wait_group %0;" :: "n"(N) : "memory");
}
__device__ __forceinline__ void ldmx4(uint32_t* r, uint32_t addr) {
    asm volatile("ldmatrix.sync.aligned.m8n8.x4.shared.b16 {%0,%1,%2,%3}, [%4];"
                 : "=r"(r[0]), "=r"(r[1]), "=r"(r[2]), "=r"(r[3]) : "r"(addr));
}
__device__ __forceinline__ void mma_f16(float* c, const uint32_t* a, const uint32_t* b) {
    asm volatile("mma.sync.aligned.m16n8k16.row.col.f32.f16.f16.f32 "
                 "{%0,%1,%2,%3}, {%4,%5,%6,%7}, {%8,%9}, {%0,%1,%2,%3};"
                 : "+f"(c[0]), "+f"(c[1]), "+f"(c[2]), "+f"(c[3])
                 : "r"(a[0]), "r"(a[1]), "r"(a[2]), "r"(a[3]), "r"(b[0]), "r"(b[1]));
}
// fp32x4 -> fp16x2 pair (hi only)
__device__ __forceinline__ uint2 cvt_h4(float4 v) {
    __half2 h0 = __floats2half2_rn(v.x, v.y);
    __half2 h1 = __floats2half2_rn(v.z, v.w);
    return make_uint2(*(uint32_t*)&h0, *(uint32_t*)&h1);
}
// fp32x4 -> hi + lo residual pairs
__device__ __forceinline__ void cvt_hl4(float4 v, uint2& hi, uint2& lo) {
    __half2 h0 = __floats2half2_rn(v.x, v.y);
    __half2 h1 = __floats2half2_rn(v.z, v.w);
    float rx = v.x - __low2float(h0),  ry = v.y - __high2float(h0);
    float rz = v.z - __low2float(h1),  rw = v.w - __high2float(h1);
    __half2 l0 = __floats2half2_rn(rx, ry);
    __half2 l1 = __floats2half2_rn(rz, rw);
    hi = make_uint2(*(uint32_t*)&h0, *(uint32_t*)&h1);
    lo = make_uint2(*(uint32_t*)&l0, *(uint32_t*)&l1);
}
__device__ __forceinline__ void split1(float v, hf& h, hf& l) {
    h = __float2half_rn(v);
    l = __float2half_rn(v - __half2float(h));
}
__device__ __forceinline__ void split2(float a, float b, uint32_t& hw, uint32_t& lw) {
    __half2 h = __floats2half2_rn(a, b);
    float ra = a - __low2float(h), rb = b - __high2float(h);
    __half2 l = __floats2half2_rn(ra, rb);
    hw = *(uint32_t*)&h;
    lw = *(uint32_t*)&l;
}

// ---------------- tile slot layout per TERMS ----------------
// TERMS==1: [Ah, Bh]            NT=2
// TERMS==3: [Ah, Al, Bh, Bl]    NT=4
template <int TERMS> struct Slots {
    static constexpr int SAh = 0;
    static constexpr int SAl = 1;                       // valid TERMS>=2
    static constexpr int SBh = (TERMS == 1) ? 1 : 2;
    static constexpr int SBl = 3;                       // valid TERMS==3
    static constexpr int NT  = (TERMS == 1) ? 2 : (TERMS == 2) ? 3 : 4;
    static constexpr int BUF = NT * TILE_B;
};

// ---------------- compute one 32-deep K tile ----------------
template <int TERMS>
__device__ __forceinline__ void compute_kt(uint32_t bb, float acc[16][4],
                                           int a_off, int b_off, int wr, int wc) {
    using S = Slots<TERMS>;
#pragma unroll
    for (int ks = 0; ks < 2; ++ks) {
        const uint32_t koff = ks * 32;
        uint32_t bh[4][2], bl[4][2];
#pragma unroll
        for (int n2 = 0; n2 < 2; ++n2) {
            const uint32_t nbase = (wc * 32 + n2 * 16) * 80 + koff + b_off;
            uint32_t r4[4];
            ldmx4(r4, bb + S::SBh * TILE_B + nbase);
            bh[n2 * 2][0] = r4[0]; bh[n2 * 2][1] = r4[1];
            bh[n2 * 2 + 1][0] = r4[2]; bh[n2 * 2 + 1][1] = r4[3];
            if (TERMS == 3) {
                ldmx4(r4, bb + S::SBl * TILE_B + nbase);
                bl[n2 * 2][0] = r4[0]; bl[n2 * 2][1] = r4[1];
                bl[n2 * 2 + 1][0] = r4[2]; bl[n2 * 2 + 1][1] = r4[3];
            }
        }
#pragma unroll
        for (int mi = 0; mi < 4; ++mi) {
            const uint32_t mbase = (wr * 64 + mi * 16) * 80 + koff + a_off;
            uint32_t ah[4], al[4];
            ldmx4(ah, bb + S::SAh * TILE_B + mbase);
            if (TERMS >= 2) ldmx4(al, bb + S::SAl * TILE_B + mbase);
#pragma unroll
            for (int ni = 0; ni < 4; ++ni) {
                mma_f16(acc[mi * 4 + ni], ah, bh[ni]);
                if (TERMS >= 2) mma_f16(acc[mi * 4 + ni], al, bh[ni]);
                if (TERMS == 3) mma_f16(acc[mi * 4 + ni], ah, bl[ni]);
            }
        }
    }
}

// issue cp.async for one fp16 tile (2x16B chunks/thread; 64B data per 80B row)
__device__ __forceinline__ void issue_tile(uint32_t bb, int tile, const hf* base,
                                           int ld, int k0, int t) {
    int row = t >> 2, q = t & 3;
    cp16(bb + tile * TILE_B + row * 80 + q * 16, base + (size_t)row * ld + k0 + q * 8);
    row = (t + 256) >> 2; q = (t + 256) & 3;
    cp16(bb + tile * TILE_B + row * 80 + q * 16, base + (size_t)row * ld + k0 + q * 8);
}

// ---------------- pre-split fp16 core (TERMS = 1 or 3) ----------------
template <int TERMS>
__device__ __forceinline__ void mm_f16_core(const hf* __restrict__ Ah,
                                            const hf* __restrict__ Al, int lda,
                                            const hf* __restrict__ Bh,
                                            const hf* __restrict__ Bl, int ldb,
                                            int ktiles, float acc[16][4]) {
    using S = Slots<TERMS>;
    extern __shared__ __align__(128) char dsm[];
    const int t = threadIdx.x, lane = t & 31, w = t >> 5;
    const int wr = w >> 2, wc = w & 3;
    const uint32_t sb = smem_u32(dsm);
    const int a_off = ((lane & 7) + ((lane >> 3) & 1) * 8) * 80 + ((lane >> 4) & 1) * 16;
    const int b_off = ((lane & 7) + ((lane >> 4) & 1) * 8) * 80 + ((lane >> 3) & 1) * 16;

#pragma unroll
    for (int i = 0; i < 16; ++i)
#pragma unroll
        for (int j = 0; j < 4; ++j) acc[i][j] = 0.0f;

    issue_tile(sb, S::SAh, Ah, lda, 0, t);
    if (TERMS >= 2) issue_tile(sb, S::SAl, Al, lda, 0, t);
    issue_tile(sb, S::SBh, Bh, ldb, 0, t);
    if (TERMS == 3) issue_tile(sb, S::SBl, Bl, ldb, 0, t);
    cp_commit();

    int cur = 0;
    for (int kt = 0; kt < ktiles; ++kt) {
        const bool more = (kt + 1 < ktiles);
        if (more) {
            const uint32_t nb = sb + (cur ^ 1) * S::BUF;
            const int k0 = (kt + 1) * KT;
            issue_tile(nb, S::SAh, Ah, lda, k0, t);
            if (TERMS >= 2) issue_tile(nb, S::SAl, Al, lda, k0, t);
            issue_tile(nb, S::SBh, Bh, ldb, k0, t);
            if (TERMS == 3) issue_tile(nb, S::SBl, Bl, ldb, k0, t);
            cp_commit();
            cp_wait<1>();
        } else {
            cp_wait<0>();
        }
        __syncthreads();
        compute_kt<TERMS>(sb + cur * S::BUF, acc, a_off, b_off, wr, wc);
        __syncthreads();
        cur ^= 1;
    }
}

// ---------------- stage-A core: single term, A fp32 in-kernel cvt ----------------
__device__ __forceinline__ void mm_a_core(const float* __restrict__ A, int lda,
                                          const hf* __restrict__ Bh, int ldb,
                                          int ktiles, float acc[16][4]) {
    using S = Slots<1>;
    extern __shared__ __align__(128) char dsm[];
    const int t = threadIdx.x, lane = t & 31, w = t >> 5;
    const int wr = w >> 2, wc = w & 3;
    const uint32_t sb = smem_u32(dsm);
    const int a_off = ((lane & 7) + ((lane >> 3) & 1) * 8) * 80 + ((lane >> 4) & 1) * 16;
    const int b_off = ((lane & 7) + ((lane >> 4) & 1) * 8) * 80 + ((lane >> 3) & 1) * 16;

#pragma unroll
    for (int i = 0; i < 16; ++i)
#pragma unroll
        for (int j = 0; j < 4; ++j) acc[i][j] = 0.0f;

    float4 av[4];
    issue_tile(sb, S::SBh, Bh, ldb, 0, t);
    cp_commit();
#pragma unroll
    for (int i = 0; i < 4; ++i) {
        const int idx = t + 256 * i, r = idx >> 3, c4 = (idx & 7) << 2;
        av[i] = *(const float4*)&A[(size_t)r * lda + c4];
    }
#pragma unroll
    for (int i = 0; i < 4; ++i) {
        const int idx = t + 256 * i, r = idx >> 3, c4 = (idx & 7) << 2;
        *(uint2*)(dsm + S::SAh * TILE_B + r * 80 + c4 * 2) = cvt_h4(av[i]);
    }

    int cur = 0;
    for (int kt = 0; kt < ktiles; ++kt) {
        const bool more = (kt + 1 < ktiles);
        if (more) {
#pragma unroll
            for (int i = 0; i < 4; ++i) {
                const int idx = t + 256 * i, r = idx >> 3, c4 = (idx & 7) << 2;
                av[i] = *(const float4*)&A[(size_t)r * lda + (kt + 1) * KT + c4];
            }
            issue_tile(sb + (cur ^ 1) * S::BUF, S::SBh, Bh, ldb, (kt + 1) * KT, t);
            cp_commit();
            cp_wait<1>();
        } else {
            cp_wait<0>();
        }
        __syncthreads();
        compute_kt<1>(sb + cur * S::BUF, acc, a_off, b_off, wr, wc);
        __syncthreads();
        if (more) {
#pragma unroll
            for (int i = 0; i < 4; ++i) {
                const int idx = t + 256 * i, r = idx >> 3, c4 = (idx & 7) << 2;
                *(uint2*)(dsm + (cur ^ 1) * S::BUF + S::SAh * TILE_B + r * 80 + c4 * 2) =
                    cvt_h4(av[i]);
            }
        }
        cur ^= 1;
    }
}

// ---------------- prep kernels ----------------
__global__ void zero_kernel() {
    int i = blockIdx.x * 256 + threadIdx.x;   // 262144 each
    g_xhatT[i] = 0.0f;
    g_y[i]     = 0.0f;
}

__global__ void __launch_bounds__(256) ht_kernel(const float* __restrict__ Aop,
                                                 const float* __restrict__ Bop,
                                                 const float* __restrict__ Dout,
                                                 const float* __restrict__ Din,
                                                 const float* __restrict__ product) {
    int j = blockIdx.x;
    int t = threadIdx.x;
    __shared__ float Aj[NR * 64];
    __shared__ float Bj[NR * 64];
    __shared__ float Qs[64 * 64];
    for (int i = t; i < NR * 64; i += 256) {
        Aj[i] = Aop[j * (NR * 64) + i];
        Bj[i] = Bop[j * (NR * 64) + i];
    }
    __syncthreads();
#pragma unroll
    for (int s = 0; s < 16; ++s) {
        int idx = t + 256 * s;
        int m = idx >> 6, n = idx & 63;
        float q = 0.0f;
#pragma unroll
        for (int r = 0; r < NR; ++r) q += Aj[r * 64 + m] * Bj[r * 64 + n];
        Qs[idx] = q;
    }
    __syncthreads();
#pragma unroll 4
    for (int s = 0; s < 64; ++s) {
        int idx = t + 256 * s;        // 16384 = 128x128
        int k = idx >> 7, l = idx & 127;
        float h = Dout[j * 128 + k] * Din[j * 128 + l] * product[k * 128 + l];
        if (k < 64 && l < 64) h += Qs[k * 64 + l];
        hf hh, ll;
        split1(h, hh, ll);
        g_Hk_h[k * (NJ * 128) + j * 128 + l] = hh;
        g_Hk_l[k * (NJ * 128) + j * 128 + l] = ll;
    }
}

__global__ void wt_kernel(const float* __restrict__ w) {
    int id = blockIdx.x * 256 + threadIdx.x;   // 262144
    int ii = id & 127;
    int o  = (id >> 7) & 127;
    int j  = id >> 14;
    hf h, l;
    split1(w[(ii * 128 + o) * NJ + j] * WSCALE, h, l);
    g_Wt_h[id] = h;
    g_Wt_l[id] = l;
}

// wbases[NPTS][128] -> wbT_h [128][NPTS] (fp16, single)
__global__ void __launch_bounds__(256) twb_kernel(const float* __restrict__ wb) {
    __shared__ float tile[32][33];
    int xb = blockIdx.x * 32, kb = blockIdx.y * 32;
    int tx = threadIdx.x & 31, ty = threadIdx.x >> 5;
#pragma unroll
    for (int i = 0; i < 32; i += 8)
        tile[ty + i][tx] = wb[(size_t)(xb + ty + i) * 128 + kb + tx];
    __syncthreads();
#pragma unroll
    for (int i = 0; i < 32; i += 8)
        g_wbT_h[(size_t)(kb + ty + i) * NPTS + xb + tx] = __float2half_rn(tile[tx][ty + i]);
}

// bases elementwise -> fp16 (single)
__global__ void __launch_bounds__(256) tbs_kernel(const float* __restrict__ bases) {
    int i4 = blockIdx.x * 256 + threadIdx.x;   // 524288 float4s
    float4 v = ((const float4*)bases)[i4];
    *(uint2*)&g_bs_h[(size_t)i4 * 4] = cvt_h4(v);
}

// fp32 -> hi/lo split for xhatT (SEL=0); y -> descaled fp16 hi only (SEL=1)
template <int SEL>
__global__ void __launch_bounds__(256) cvt_big_kernel() {
    int i4 = blockIdx.x * 256 + threadIdx.x;   // 65536 float4s
    if (SEL == 0) {
        float4 v = ((const float4*)g_xhatT)[i4];
        uint2 hi, lo;
        cvt_hl4(v, hi, lo);
        *(uint2*)&g_xhT_h[(size_t)i4 * 4] = hi;
        *(uint2*)&g_xhT_l[(size_t)i4 * 4] = lo;
    } else {
        float4 v = ((const float4*)g_y)[i4];
        v.x *= WINV; v.y *= WINV; v.z *= WINV; v.w *= WINV;
        *(uint2*)&g_y_h[(size_t)i4 * 4] = cvt_h4(v);
    }
}

// ---------------- GEMM stage kernels ----------------
// stage A: xhatT[b][l][i] += x[(b,i),:] @ wbT  (16 b-blocks x 16 K-splits, 1-term)
__global__ void __launch_bounds__(256) k_mm_a(const float* __restrict__ x) {
    const int b  = blockIdx.x;
    const int ks = blockIdx.y;                 // 16 splits x 1024 K
    float acc[16][4];
    mm_a_core(x + (size_t)(b * 128) * NPTS + ks * 1024, NPTS,
              g_wbT_h + ks * 1024, NPTS, 32, acc);
    const int lane = threadIdx.x & 31, w = threadIdx.x >> 5;
    const int wr = w >> 2, wc = w & 3;
    float* dst = g_xhatT + (size_t)b * 16384;
#pragma unroll
    for (int mi = 0; mi < 4; ++mi)
#pragma unroll
        for (int ni = 0; ni < 4; ++ni) {
            const int row = wr * 64 + mi * 16 + (lane >> 2);   // i
            const int col = wc * 32 + ni * 8 + (lane & 3) * 2; // l
            const float* a = acc[mi * 4 + ni];
            atomicAdd(&dst[(col + 0) * 128 + row],     a[0]);
            atomicAdd(&dst[(col + 1) * 128 + row],     a[1]);
            atomicAdd(&dst[(col + 0) * 128 + row + 8], a[2]);
            atomicAdd(&dst[(col + 1) * 128 + row + 8], a[3]);
        }
}

// stage Z: z[(b,o)][(j,l)] = Wt'[j] @ xhatT[b]^T (3-term), stored split fp16
__global__ void __launch_bounds__(256) k_mm_z() {
    const int b = blockIdx.x >> 4, j = blockIdx.x & 15;
    float acc[16][4];
    mm_f16_core<3>(g_Wt_h + (size_t)j * 16384, g_Wt_l + (size_t)j * 16384, 128,
                   g_xhT_h + (size_t)b * 16384, g_xhT_l + (size_t)b * 16384, 128, 4, acc);
    const int lane = threadIdx.x & 31, w = threadIdx.x >> 5;
    const int wr = w >> 2, wc = w & 3;
#pragma unroll
    for (int mi = 0; mi < 4; ++mi)
#pragma unroll
        for (int ni = 0; ni < 4; ++ni) {
            const int row = wr * 64 + mi * 16 + (lane >> 2);   // o
            const int col = wc * 32 + ni * 8 + (lane & 3) * 2; // l
            const float* a = acc[mi * 4 + ni];
            uint32_t hw, lw;
            size_t idx0 = (size_t)(b * 128 + row) * 2048 + j * 128 + col;
            split2(a[0], a[1], hw, lw);
            *(uint32_t*)&g_z_h[idx0] = hw;
            *(uint32_t*)&g_z_l[idx0] = lw;
            size_t idx1 = idx0 + (size_t)8 * 2048;
            split2(a[2], a[3], hw, lw);
            *(uint32_t*)&g_z_h[idx1] = hw;
            *(uint32_t*)&g_z_l[idx1] = lw;
        }
}

// stage Y: y[(b,o)][k] += z @ Hk (3-term; 16 row-blocks x 8 K-splits)
__global__ void __launch_bounds__(256) k_mm_y() {
    const int row0 = blockIdx.x * 128;
    const int kt0  = blockIdx.y * 8;
    float acc[16][4];
    mm_f16_core<3>(g_z_h + (size_t)row0 * 2048 + kt0 * KT,
                   g_z_l + (size_t)row0 * 2048 + kt0 * KT, 2048,
                   g_Hk_h + kt0 * KT, g_Hk_l + kt0 * KT, 2048, 8, acc);
    const int lane = threadIdx.x & 31, w = threadIdx.x >> 5;
    const int wr = w >> 2, wc = w & 3;
#pragma unroll
    for (int mi = 0; mi < 4; ++mi)
#pragma unroll
        for (int ni = 0; ni < 4; ++ni) {
            const int row = row0 + wr * 64 + mi * 16 + (lane >> 2);
            const int col = wc * 32 + ni * 8 + (lane & 3) * 2;
            const float* a = acc[mi * 4 + ni];
            atomicAdd(&g_y[(size_t)row * 128 + col],           a[0]);
            atomicAdd(&g_y[(size_t)row * 128 + col + 1],       a[1]);
            atomicAdd(&g_y[(size_t)(row + 8) * 128 + col],     a[2]);
            atomicAdd(&g_y[(size_t)(row + 8) * 128 + col + 1], a[3]);
        }
}

// stage D: out = y_h @ bases_h^T (1-term)
__global__ void __launch_bounds__(256) k_mm_d(float* __restrict__ out) {
    const int row0 = blockIdx.x * 128;
    const int x0   = blockIdx.y * 128;
    float acc[16][4];
    mm_f16_core<1>(g_y_h + (size_t)row0 * 128, (const hf*)nullptr, 128,
                   g_bs_h + (size_t)x0 * 128, (const hf*)nullptr, 128, 4, acc);
    const int lane = threadIdx.x & 31, w = threadIdx.x >> 5;
    const int wr = w >> 2, wc = w & 3;
#pragma unroll
    for (int mi = 0; mi < 4; ++mi)
#pragma unroll
        for (int ni = 0; ni < 4; ++ni) {
            const int row = row0 + wr * 64 + mi * 16 + (lane >> 2);
            const int col = x0 + wc * 32 + ni * 8 + (lane & 3) * 2;
            const float* a = acc[mi * 4 + ni];
            *(float2*)&out[(size_t)row * NPTS + col]       = make_float2(a[0], a[1]);
            *(float2*)&out[(size_t)(row + 8) * NPTS + col] = make_float2(a[2], a[3]);
        }
}

// ---------------- launch ----------------
extern "C" void kernel_launch(void* const* d_in, const int* in_sizes, int n_in,
                              void* d_out, int out_size) {
    const float* x       = (const float*)d_in[0];
    const float* bases   = (const float*)d_in[1];
    const float* wbases  = (const float*)d_in[2];
    const float* product = (const float*)d_in[3];
    const float* Dout    = (const float*)d_in[4];
    const float* Din     = (const float*)d_in[5];
    const float* Aop     = (const float*)d_in[6];
    const float* Bop     = (const float*)d_in[7];
    const float* weights = (const float*)d_in[8];
    float* out = (float*)d_out;

    const int SM_1 = 2 * Slots<1>::BUF;   // 40960
    const int SM_3 = 2 * Slots<3>::BUF;   // 81920
    cudaFuncSetAttribute(k_mm_a, cudaFuncAttributeMaxDynamicSharedMemorySize, SM_1);
    cudaFuncSetAttribute(k_mm_z, cudaFuncAttributeMaxDynamicSharedMemorySize, SM_3);
    cudaFuncSetAttribute(k_mm_y, cudaFuncAttributeMaxDynamicSharedMemorySize, SM_3);
    cudaFuncSetAttribute(k_mm_d, cudaFuncAttributeMaxDynamicSharedMemorySize, SM_1);

    zero_kernel<<<1024, 256>>>();
    ht_kernel<<<NJ, 256>>>(Aop, Bop, Dout, Din, product);
    wt_kernel<<<1024, 256>>>(weights);
    twb_kernel<<<dim3(NPTS / 32, 4), 256>>>(wbases);
    tbs_kernel<<<2048, 256>>>(bases);

    k_mm_a<<<dim3(16, 16), 256, SM_1>>>(x);
    cvt_big_kernel<0><<<256, 256>>>();
    k_mm_z<<<NB * NJ, 256, SM_3>>>();
    k_mm_y<<<dim3(16, 8), 256, SM_3>>>();
    cvt_big_kernel<1><<<256, 256>>>();
    k_mm_d<<<dim3(16, 128), 256, SM_1>>>(out);
}

// round 13
// speedup vs baseline: 1.6393x; 1.5698x over previous
#include <cuda_runtime.h>
#include <cuda_fp16.h>
#include <cstdint>

#define NB    16
#define NDIM  128
#define NPTS  16384
#define NJ    16
#define NR    8
#define KT    32                     // K-tile depth
#define ROWPAD 40                    // padded smem row (elements)
#define TILE_B (128 * ROWPAD * 2)    // 10240 bytes per fp16 tile
#define WSCALE 16384.0f
#define WINV   (1.0f / 16384.0f)

typedef __half hf;

// ---------------- device scratch ----------------
__device__ __align__(16) float g_xhatT[NB * 128 * 128];      // [b][l][i]  1 MB
__device__ __align__(16) float g_y    [NB * 128 * 128];      // [(b,o)][k] 1 MB (scaled 2^14)
__device__ __align__(16) hf g_xhT_h[NB * 128 * 128];                             // [b][l][i]
__device__ __align__(16) hf g_Wt_h [NJ * 128 * 128], g_Wt_l [NJ * 128 * 128];   // [j][o][i] (x 2^14)
__device__ __align__(16) hf g_Hk_h [128 * NJ * 128];                             // [k][(j,l)]
__device__ __align__(16) hf g_y_h  [2048 * 128];                                 // descaled fp16
__device__ __align__(16) hf g_wbT_h[128 * NPTS];                                 // [l][x]
__device__ __align__(16) hf g_bs_h [NPTS * 128];                                 // [x][k]

// ---------------- helpers ----------------
__device__ __forceinline__ uint32_t smem_u32(const void* p) {
    uint32_t a;
    asm("{ .reg .u64 t; cvta.to.shared.u64 t, %1; cvt.u32.u64 %0, t; }" : "=r"(a) : "l"(p));
    return a;
}
__device__ __forceinline__ void cp16(uint32_t dst, const void* src) {
    asm volatile("cp.async.cg.shared.global [%0], [%1], 16;" :: "r"(dst), "l"(src));
}
__device__ __forceinline__ void cp_commit() {
    asm volatile("cp.async.commit_group;" ::: "memory");
}
template <int N>
__device__ __forceinline__ void cp_wait() {
    asm volatile("cp.async.wait_group %0;" :: "n"(N) : "memory");
}
__device__ __forceinline__ void ldmx4(uint32_t* r, uint32_t addr) {
    asm volatile("ldmatrix.sync.aligned.m8n8.x4.shared.b16 {%0,%1,%2,%3}, [%4];"
                 : "=r"(r[0]), "=r"(r[1]), "=r"(r[2]), "=r"(r[3]) : "r"(addr));
}
__device__ __forceinline__ void mma_f16(float* c, const uint32_t* a, const uint32_t* b) {
    asm volatile("mma.sync.aligned.m16n8k16.row.col.f32.f16.f16.f32 "
                 "{%0,%1,%2,%3}, {%4,%5,%6,%7}, {%8,%9}, {%0,%1,%2,%3};"
                 : "+f"(c[0]), "+f"(c[1]), "+f"(c[2]), "+f"(c[3])
                 : "r"(a[0]), "r"(a[1]), "r"(a[2]), "r"(a[3]), "r"(b[0]), "r"(b[1]));
}
// fp32x4 -> fp16x2 pair (hi only)
__device__ __forceinline__ uint2 cvt_h4(float4 v) {
    __half2 h0 = __floats2half2_rn(v.x, v.y);
    __half2 h1 = __floats2half2_rn(v.z, v.w);
    return make_uint2(*(uint32_t*)&h0, *(uint32_t*)&h1);
}
__device__ __forceinline__ void split1(float v, hf& h, hf& l) {
    h = __float2half_rn(v);
    l = __float2half_rn(v - __half2float(h));
}
__device__ __forceinline__ void split2(float a, float b, uint32_t& hw, uint32_t& lw) {
    __half2 h = __floats2half2_rn(a, b);
    float ra = a - __low2float(h), rb = b - __high2float(h);
    __half2 l = __floats2half2_rn(ra, rb);
    hw = *(uint32_t*)&h;
    lw = *(uint32_t*)&l;
}

// ---------------- tile slot layout per TERMS ----------------
// TERMS==1: [Ah, Bh] NT=2   TERMS==2: [Ah, Al, Bh] NT=3   TERMS==3: +Bl NT=4
template <int TERMS> struct Slots {
    static constexpr int SAh = 0;
    static constexpr int SAl = 1;
    static constexpr int SBh = (TERMS == 1) ? 1 : 2;
    static constexpr int SBl = 3;
    static constexpr int NT  = (TERMS == 1) ? 2 : (TERMS == 2) ? 3 : 4;
    static constexpr int BUF = NT * TILE_B;
};

// ---------------- compute one 32-deep K tile ----------------
template <int TERMS>
__device__ __forceinline__ void compute_kt(uint32_t bb, float acc[16][4],
                                           int a_off, int b_off, int wr, int wc) {
    using S = Slots<TERMS>;
#pragma unroll
    for (int ks = 0; ks < 2; ++ks) {
        const uint32_t koff = ks * 32;
        uint32_t bh[4][2], bl[4][2];
#pragma unroll
        for (int n2 = 0; n2 < 2; ++n2) {
            const uint32_t nbase = (wc * 32 + n2 * 16) * 80 + koff + b_off;
            uint32_t r4[4];
            ldmx4(r4, bb + S::SBh * TILE_B + nbase);
            bh[n2 * 2][0] = r4[0]; bh[n2 * 2][1] = r4[1];
            bh[n2 * 2 + 1][0] = r4[2]; bh[n2 * 2 + 1][1] = r4[3];
            if (TERMS == 3) {
                ldmx4(r4, bb + S::SBl * TILE_B + nbase);
                bl[n2 * 2][0] = r4[0]; bl[n2 * 2][1] = r4[1];
                bl[n2 * 2 + 1][0] = r4[2]; bl[n2 * 2 + 1][1] = r4[3];
            }
        }
#pragma unroll
        for (int mi = 0; mi < 4; ++mi) {
            const uint32_t mbase = (wr * 64 + mi * 16) * 80 + koff + a_off;
            uint32_t ah[4], al[4];
            ldmx4(ah, bb + S::SAh * TILE_B + mbase);
            if (TERMS >= 2) ldmx4(al, bb + S::SAl * TILE_B + mbase);
#pragma unroll
            for (int ni = 0; ni < 4; ++ni) {
                mma_f16(acc[mi * 4 + ni], ah, bh[ni]);
                if (TERMS >= 2) mma_f16(acc[mi * 4 + ni], al, bh[ni]);
                if (TERMS == 3) mma_f16(acc[mi * 4 + ni], ah, bl[ni]);
            }
        }
    }
}

// issue cp.async for one fp16 tile (2x16B chunks/thread; 64B data per 80B row)
__device__ __forceinline__ void issue_tile(uint32_t bb, int tile, const hf* base,
                                           int ld, int k0, int t) {
    int row = t >> 2, q = t & 3;
    cp16(bb + tile * TILE_B + row * 80 + q * 16, base + (size_t)row * ld + k0 + q * 8);
    row = (t + 256) >> 2; q = (t + 256) & 3;
    cp16(bb + tile * TILE_B + row * 80 + q * 16, base + (size_t)row * ld + k0 + q * 8);
}

// ---------------- pre-split fp16 core (TERMS = 1, 2 or 3) ----------------
template <int TERMS>
__device__ __forceinline__ void mm_f16_core(const hf* __restrict__ Ah,
                                            const hf* __restrict__ Al, int lda,
                                            const hf* __restrict__ Bh,
                                            const hf* __restrict__ Bl, int ldb,
                                            int ktiles, float acc[16][4]) {
    using S = Slots<TERMS>;
    extern __shared__ __align__(128) char dsm[];
    const int t = threadIdx.x, lane = t & 31, w = t >> 5;
    const int wr = w >> 2, wc = w & 3;
    const uint32_t sb = smem_u32(dsm);
    const int a_off = ((lane & 7) + ((lane >> 3) & 1) * 8) * 80 + ((lane >> 4) & 1) * 16;
    const int b_off = ((lane & 7) + ((lane >> 4) & 1) * 8) * 80 + ((lane >> 3) & 1) * 16;

#pragma unroll
    for (int i = 0; i < 16; ++i)
#pragma unroll
        for (int j = 0; j < 4; ++j) acc[i][j] = 0.0f;

    issue_tile(sb, S::SAh, Ah, lda, 0, t);
    if (TERMS >= 2) issue_tile(sb, S::SAl, Al, lda, 0, t);
    issue_tile(sb, S::SBh, Bh, ldb, 0, t);
    if (TERMS == 3) issue_tile(sb, S::SBl, Bl, ldb, 0, t);
    cp_commit();

    int cur = 0;
    for (int kt = 0; kt < ktiles; ++kt) {
        const bool more = (kt + 1 < ktiles);
        if (more) {
            const uint32_t nb = sb + (cur ^ 1) * S::BUF;
            const int k0 = (kt + 1) * KT;
            issue_tile(nb, S::SAh, Ah, lda, k0, t);
            if (TERMS >= 2) issue_tile(nb, S::SAl, Al, lda, k0, t);
            issue_tile(nb, S::SBh, Bh, ldb, k0, t);
            if (TERMS == 3) issue_tile(nb, S::SBl, Bl, ldb, k0, t);
            cp_commit();
            cp_wait<1>();
        } else {
            cp_wait<0>();
        }
        __syncthreads();
        compute_kt<TERMS>(sb + cur * S::BUF, acc, a_off, b_off, wr, wc);
        __syncthreads();
        cur ^= 1;
    }
}

// ---------------- stage-A core: single term, A fp32 in-kernel cvt ----------------
__device__ __forceinline__ void mm_a_core(const float* __restrict__ A, int lda,
                                          const hf* __restrict__ Bh, int ldb,
                                          int ktiles, float acc[16][4]) {
    using S = Slots<1>;
    extern __shared__ __align__(128) char dsm[];
    const int t = threadIdx.x, lane = t & 31, w = t >> 5;
    const int wr = w >> 2, wc = w & 3;
    const uint32_t sb = smem_u32(dsm);
    const int a_off = ((lane & 7) + ((lane >> 3) & 1) * 8) * 80 + ((lane >> 4) & 1) * 16;
    const int b_off = ((lane & 7) + ((lane >> 4) & 1) * 8) * 80 + ((lane >> 3) & 1) * 16;

#pragma unroll
    for (int i = 0; i < 16; ++i)
#pragma unroll
        for (int j = 0; j < 4; ++j) acc[i][j] = 0.0f;

    float4 av[4];
    issue_tile(sb, S::SBh, Bh, ldb, 0, t);
    cp_commit();
#pragma unroll
    for (int i = 0; i < 4; ++i) {
        const int idx = t + 256 * i, r = idx >> 3, c4 = (idx & 7) << 2;
        av[i] = *(const float4*)&A[(size_t)r * lda + c4];
    }
#pragma unroll
    for (int i = 0; i < 4; ++i) {
        const int idx = t + 256 * i, r = idx >> 3, c4 = (idx & 7) << 2;
        *(uint2*)(dsm + S::SAh * TILE_B + r * 80 + c4 * 2) = cvt_h4(av[i]);
    }

    int cur = 0;
    for (int kt = 0; kt < ktiles; ++kt) {
        const bool more = (kt + 1 < ktiles);
        if (more) {
#pragma unroll
            for (int i = 0; i < 4; ++i) {
                const int idx = t + 256 * i, r = idx >> 3, c4 = (idx & 7) << 2;
                av[i] = *(const float4*)&A[(size_t)r * lda + (kt + 1) * KT + c4];
            }
            issue_tile(sb + (cur ^ 1) * S::BUF, S::SBh, Bh, ldb, (kt + 1) * KT, t);
            cp_commit();
            cp_wait<1>();
        } else {
            cp_wait<0>();
        }
        __syncthreads();
        compute_kt<1>(sb + cur * S::BUF, acc, a_off, b_off, wr, wc);
        __syncthreads();
        if (more) {
#pragma unroll
            for (int i = 0; i < 4; ++i) {
                const int idx = t + 256 * i, r = idx >> 3, c4 = (idx & 7) << 2;
                *(uint2*)(dsm + (cur ^ 1) * S::BUF + S::SAh * TILE_B + r * 80 + c4 * 2) =
                    cvt_h4(av[i]);
            }
        }
        cur ^= 1;
    }
}

// ---------------- prep kernels ----------------
__global__ void __launch_bounds__(256) ht_kernel(const float* __restrict__ Aop,
                                                 const float* __restrict__ Bop,
                                                 const float* __restrict__ Dout,
                                                 const float* __restrict__ Din,
                                                 const float* __restrict__ product) {
    int j = blockIdx.x;
    int t = threadIdx.x;
    __shared__ float Aj[NR * 64];
    __shared__ float Bj[NR * 64];
    __shared__ float Qs[64 * 64];
    for (int i = t; i < NR * 64; i += 256) {
        Aj[i] = Aop[j * (NR * 64) + i];
        Bj[i] = Bop[j * (NR * 64) + i];
    }
    __syncthreads();
#pragma unroll
    for (int s = 0; s < 16; ++s) {
        int idx = t + 256 * s;
        int m = idx >> 6, n = idx & 63;
        float q = 0.0f;
#pragma unroll
        for (int r = 0; r < NR; ++r) q += Aj[r * 64 + m] * Bj[r * 64 + n];
        Qs[idx] = q;
    }
    __syncthreads();
#pragma unroll 4
    for (int s = 0; s < 64; ++s) {
        int idx = t + 256 * s;        // 16384 = 128x128
        int k = idx >> 7, l = idx & 127;
        float h = Dout[j * 128 + k] * Din[j * 128 + l] * product[k * 128 + l];
        if (k < 64 && l < 64) h += Qs[k * 64 + l];
        g_Hk_h[k * (NJ * 128) + j * 128 + l] = __float2half_rn(h);
    }
}

// weights split (+ zero xhatT / y accumulators — same index space)
__global__ void wt_kernel(const float* __restrict__ w) {
    int id = blockIdx.x * 256 + threadIdx.x;   // 262144
    g_xhatT[id] = 0.0f;
    g_y[id]     = 0.0f;
    int ii = id & 127;
    int o  = (id >> 7) & 127;
    int j  = id >> 14;
    hf h, l;
    split1(w[(ii * 128 + o) * NJ + j] * WSCALE, h, l);
    g_Wt_h[id] = h;
    g_Wt_l[id] = l;
}

// wbases[NPTS][128] -> wbT_h [128][NPTS] (fp16, single)
__global__ void __launch_bounds__(256) twb_kernel(const float* __restrict__ wb) {
    __shared__ float tile[32][33];
    int xb = blockIdx.x * 32, kb = blockIdx.y * 32;
    int tx = threadIdx.x & 31, ty = threadIdx.x >> 5;
#pragma unroll
    for (int i = 0; i < 32; i += 8)
        tile[ty + i][tx] = wb[(size_t)(xb + ty + i) * 128 + kb + tx];
    __syncthreads();
#pragma unroll
    for (int i = 0; i < 32; i += 8)
        g_wbT_h[(size_t)(kb + ty + i) * NPTS + xb + tx] = __float2half_rn(tile[tx][ty + i]);
}

// bases elementwise -> fp16 (single)
__global__ void __launch_bounds__(256) tbs_kernel(const float* __restrict__ bases) {
    int i4 = blockIdx.x * 256 + threadIdx.x;   // 524288 float4s
    float4 v = ((const float4*)bases)[i4];
    *(uint2*)&g_bs_h[(size_t)i4 * 4] = cvt_h4(v);
}

// fp32 -> fp16 hi: xhatT (SEL=0); y descaled (SEL=1)
template <int SEL>
__global__ void __launch_bounds__(256) cvt_big_kernel() {
    int i4 = blockIdx.x * 256 + threadIdx.x;   // 65536 float4s
    if (SEL == 0) {
        float4 v = ((const float4*)g_xhatT)[i4];
        *(uint2*)&g_xhT_h[(size_t)i4 * 4] = cvt_h4(v);
    } else {
        float4 v = ((const float4*)g_y)[i4];
        v.x *= WINV; v.y *= WINV; v.z *= WINV; v.w *= WINV;
        *(uint2*)&g_y_h[(size_t)i4 * 4] = cvt_h4(v);
    }
}

// ---------------- GEMM stage kernels ----------------
// stage A: xhatT[b][l][i] += x[(b,i),:] @ wbT  (16 b-blocks x 16 K-splits, 1-term)
__global__ void __launch_bounds__(256) k_mm_a(const float* __restrict__ x) {
    const int b  = blockIdx.x;
    const int ks = blockIdx.y;                 // 16 splits x 1024 K
    float acc[16][4];
    mm_a_core(x + (size_t)(b * 128) * NPTS + ks * 1024, NPTS,
              g_wbT_h + ks * 1024, NPTS, 32, acc);
    const int lane = threadIdx.x & 31, w = threadIdx.x >> 5;
    const int wr = w >> 2, wc = w & 3;
    float* dst = g_xhatT + (size_t)b * 16384;
#pragma unroll
    for (int mi = 0; mi < 4; ++mi)
#pragma unroll
        for (int ni = 0; ni < 4; ++ni) {
            const int row = wr * 64 + mi * 16 + (lane >> 2);   // i
            const int col = wc * 32 + ni * 8 + (lane & 3) * 2; // l
            const float* a = acc[mi * 4 + ni];
            atomicAdd(&dst[(col + 0) * 128 + row],     a[0]);
            atomicAdd(&dst[(col + 1) * 128 + row],     a[1]);
            atomicAdd(&dst[(col + 0) * 128 + row + 8], a[2]);
            atomicAdd(&dst[(col + 1) * 128 + row + 8], a[3]);
        }
}

// fused stage ZY: per (b,j): ztile = Wt'[j](hi/lo) @ xhat_h[b]; y += ztile(hi/lo) @ Hk_h[j]
// smem layout:
//   [0, 61440)                GEMM1 double buffers (Slots<2>)
//   [61440, 61440+4*TILE_B)   ztile HI: 4 K-tiles (128 x 32 each, 80B rows)
//   [+4*TILE_B, +8*TILE_B)    ztile LO: 4 K-tiles
#define ZY_ZH   (2 * Slots<2>::BUF)            // 61440
#define ZY_ZL   (ZY_ZH + 4 * TILE_B)           // 102400
#define ZY_SMEM (ZY_ZL + 4 * TILE_B)           // 143360
__global__ void __launch_bounds__(256) k_mm_zy() {
    extern __shared__ __align__(128) char dsm[];
    const int b = blockIdx.x >> 4, j = blockIdx.x & 15;
    const int t = threadIdx.x, lane = t & 31, w = t >> 5;
    const int wr = w >> 2, wc = w & 3;
    const uint32_t sb = smem_u32(dsm);
    const int a_off = ((lane & 7) + ((lane >> 3) & 1) * 8) * 80 + ((lane >> 4) & 1) * 16;
    const int b_off = ((lane & 7) + ((lane >> 4) & 1) * 8) * 80 + ((lane >> 3) & 1) * 16;

    float acc[16][4];
    // ---- GEMM1: Wt_j (hi/lo) @ xhat_h[b]  -> acc (o x l) ----
    mm_f16_core<2>(g_Wt_h + (size_t)j * 16384, g_Wt_l + (size_t)j * 16384, 128,
                   g_xhT_h + (size_t)b * 16384, (const hf*)nullptr, 128, 4, acc);

    // ---- store ztile to smem, K-tile-blocked: tile index = wc (= col>>5) ----
#pragma unroll
    for (int mi = 0; mi < 4; ++mi)
#pragma unroll
        for (int ni = 0; ni < 4; ++ni) {
            const int row = wr * 64 + mi * 16 + (lane >> 2);      // o
            const int tc  = (ni * 8 + (lane & 3) * 2) * 2;        // byte col within tile
            const uint32_t hoff = ZY_ZH + wc * TILE_B + row * 80 + tc;
            const uint32_t loff = ZY_ZL + wc * TILE_B + row * 80 + tc;
            const float* a = acc[mi * 4 + ni];
            uint32_t hw, lw;
            split2(a[0], a[1], hw, lw);
            *(uint32_t*)(dsm + hoff) = hw;
            *(uint32_t*)(dsm + loff) = lw;
            split2(a[2], a[3], hw, lw);
            *(uint32_t*)(dsm + hoff + 8 * 80) = hw;
            *(uint32_t*)(dsm + loff + 8 * 80) = lw;
        }

    // ---- GEMM2: ztile (hi/lo, resident) @ Hk_h[j] (rows k, contraction l) -> y ----
#pragma unroll
    for (int i = 0; i < 16; ++i)
#pragma unroll
        for (int q = 0; q < 4; ++q) acc[i][q] = 0.0f;

    const hf* Bh = g_Hk_h + j * 128;     // row k: stride NJ*128 = 2048
    issue_tile(sb, 0, Bh, 2048, 0, t);   // reuse GEMM1 buffer slot 0
    cp_commit();

    int cur = 0;
    for (int kt = 0; kt < 4; ++kt) {
        const bool more = (kt + 1 < 4);
        if (more) {
            issue_tile(sb, cur ^ 1, Bh, 2048, (kt + 1) * KT, t);
            cp_commit();
            cp_wait<1>();
        } else {
            cp_wait<0>();
        }
        __syncthreads();     // covers ztile visibility (first iter) + B arrival
        const uint32_t bb = sb + cur * TILE_B;
        const uint32_t zh = sb + ZY_ZH + kt * TILE_B;
        const uint32_t zl = sb + ZY_ZL + kt * TILE_B;
#pragma unroll
        for (int ks = 0; ks < 2; ++ks) {
            const uint32_t koff = ks * 32;
            uint32_t bh4[4][2];
#pragma unroll
            for (int n2 = 0; n2 < 2; ++n2) {
                uint32_t r4[4];
                ldmx4(r4, bb + (wc * 32 + n2 * 16) * 80 + koff + b_off);
                bh4[n2 * 2][0] = r4[0]; bh4[n2 * 2][1] = r4[1];
                bh4[n2 * 2 + 1][0] = r4[2]; bh4[n2 * 2 + 1][1] = r4[3];
            }
#pragma unroll
            for (int mi = 0; mi < 4; ++mi) {
                const uint32_t mbase = (wr * 64 + mi * 16) * 80 + koff + a_off;
                uint32_t ah[4], al[4];
                ldmx4(ah, zh + mbase);
                ldmx4(al, zl + mbase);
#pragma unroll
                for (int ni = 0; ni < 4; ++ni) {
                    mma_f16(acc[mi * 4 + ni], ah, bh4[ni]);
                    mma_f16(acc[mi * 4 + ni], al, bh4[ni]);
                }
            }
        }
        __syncthreads();
        cur ^= 1;
    }

    // ---- epilogue: atomic accumulate into g_y ----
#pragma unroll
    for (int mi = 0; mi < 4; ++mi)
#pragma unroll
        for (int ni = 0; ni < 4; ++ni) {
            const int row = b * 128 + wr * 64 + mi * 16 + (lane >> 2);  // (b,o)
            const int col = wc * 32 + ni * 8 + (lane & 3) * 2;          // k
            const float* a = acc[mi * 4 + ni];
            atomicAdd(&g_y[(size_t)row * 128 + col],           a[0]);
            atomicAdd(&g_y[(size_t)row * 128 + col + 1],       a[1]);
            atomicAdd(&g_y[(size_t)(row + 8) * 128 + col],     a[2]);
            atomicAdd(&g_y[(size_t)(row + 8) * 128 + col + 1], a[3]);
        }
}

// stage D: out = y_h @ bases_h^T (1-term)
__global__ void __launch_bounds__(256) k_mm_d(float* __restrict__ out) {
    const int row0 = blockIdx.x * 128;
    const int x0   = blockIdx.y * 128;
    float acc[16][4];
    mm_f16_core<1>(g_y_h + (size_t)row0 * 128, (const hf*)nullptr, 128,
                   g_bs_h + (size_t)x0 * 128, (const hf*)nullptr, 128, 4, acc);
    const int lane = threadIdx.x & 31, w = threadIdx.x >> 5;
    const int wr = w >> 2, wc = w & 3;
#pragma unroll
    for (int mi = 0; mi < 4; ++mi)
#pragma unroll
        for (int ni = 0; ni < 4; ++ni) {
            const int row = row0 + wr * 64 + mi * 16 + (lane >> 2);
            const int col = x0 + wc * 32 + ni * 8 + (lane & 3) * 2;
            const float* a = acc[mi * 4 + ni];
            *(float2*)&out[(size_t)row * NPTS + col]       = make_float2(a[0], a[1]);
            *(float2*)&out[(size_t)(row + 8) * NPTS + col] = make_float2(a[2], a[3]);
        }
}

// ---------------- launch ----------------
extern "C" void kernel_launch(void* const* d_in, const int* in_sizes, int n_in,
                              void* d_out, int out_size) {
    const float* x       = (const float*)d_in[0];
    const float* bases   = (const float*)d_in[1];
    const float* wbases  = (const float*)d_in[2];
    const float* product = (const float*)d_in[3];
    const float* Dout    = (const float*)d_in[4];
    const float* Din     = (const float*)d_in[5];
    const float* Aop     = (const float*)d_in[6];
    const float* Bop     = (const float*)d_in[7];
    const float* weights = (const float*)d_in[8];
    float* out = (float*)d_out;

    const int SM_1 = 2 * Slots<1>::BUF;   // 40960
    cudaFuncSetAttribute(k_mm_a,  cudaFuncAttributeMaxDynamicSharedMemorySize, SM_1);
    cudaFuncSetAttribute(k_mm_zy, cudaFuncAttributeMaxDynamicSharedMemorySize, ZY_SMEM);
    cudaFuncSetAttribute(k_mm_d,  cudaFuncAttributeMaxDynamicSharedMemorySize, SM_1);

    ht_kernel<<<NJ, 256>>>(Aop, Bop, Dout, Din, product);
    wt_kernel<<<1024, 256>>>(weights);            // also zeroes g_xhatT, g_y
    twb_kernel<<<dim3(NPTS / 32, 4), 256>>>(wbases);
    tbs_kernel<<<2048, 256>>>(bases);

    k_mm_a<<<dim3(16, 16), 256, SM_1>>>(x);
    cvt_big_kernel<0><<<256, 256>>>();
    k_mm_zy<<<NB * NJ, 256, ZY_SMEM>>>();
    cvt_big_kernel<1><<<256, 256>>>();
    k_mm_d<<<dim3(16, 128), 256, SM_1>>>(out);
}

// round 14
// speedup vs baseline: 1.6861x; 1.0286x over previous
#include <cuda_runtime.h>
#include <cuda_fp16.h>
#include <cstdint>

#define NB    16
#define NDIM  128
#define NPTS  16384
#define NJ    16
#define NR    8
#define KT    32                     // K-tile depth
#define TILE_B (128 * 40 * 2)        // 10240 bytes per fp16 tile (80B rows)
#define WSCALE 16384.0f
#define WINV   (1.0f / 16384.0f)

typedef __half hf;

// ---------------- device scratch ----------------
__device__ __align__(16) float g_xhatT[NB * 128 * 128];      // [b][l][i]  1 MB
__device__ __align__(16) float g_y    [NB * 128 * 128];      // [(b,o)][k] 1 MB (scaled 2^14)
__device__ __align__(16) hf g_xhT_h[NB * 128 * 128];         // [b][l][i]
__device__ __align__(16) hf g_Wt_h [NJ * 128 * 128];         // [j][o][i] (x 2^14)
__device__ __align__(16) hf g_Hk_h [128 * NJ * 128];         // [k][(j,l)]
__device__ __align__(16) hf g_wbT_h[128 * NPTS];             // [l][x]
__device__ __align__(16) hf g_bs_h [NPTS * 128];             // [x][k]

// ---------------- helpers ----------------
__device__ __forceinline__ uint32_t smem_u32(const void* p) {
    uint32_t a;
    asm("{ .reg .u64 t; cvta.to.shared.u64 t, %1; cvt.u32.u64 %0, t; }" : "=r"(a) : "l"(p));
    return a;
}
__device__ __forceinline__ void cp16(uint32_t dst, const void* src) {
    asm volatile("cp.async.cg.shared.global [%0], [%1], 16;" :: "r"(dst), "l"(src));
}
__device__ __forceinline__ void cp_commit() {
    asm volatile("cp.async.commit_group;" ::: "memory");
}
template <int N>
__device__ __forceinline__ void cp_wait() {
    asm volatile("cp.async.wait_group %0;" :: "n"(N) : "memory");
}
__device__ __forceinline__ void ldmx4(uint32_t* r, uint32_t addr) {
    asm volatile("ldmatrix.sync.aligned.m8n8.x4.shared.b16 {%0,%1,%2,%3}, [%4];"
                 : "=r"(r[0]), "=r"(r[1]), "=r"(r[2]), "=r"(r[3]) : "r"(addr));
}
__device__ __forceinline__ void mma_f16(float* c, const uint32_t* a, const uint32_t* b) {
    asm volatile("mma.sync.aligned.m16n8k16.row.col.f32.f16.f16.f32 "
                 "{%0,%1,%2,%3}, {%4,%5,%6,%7}, {%8,%9}, {%0,%1,%2,%3};"
                 : "+f"(c[0]), "+f"(c[1]), "+f"(c[2]), "+f"(c[3])
                 : "r"(a[0]), "r"(a[1]), "r"(a[2]), "r"(a[3]), "r"(b[0]), "r"(b[1]));
}
__device__ __forceinline__ uint2 cvt_h4(float4 v) {
    __half2 h0 = __floats2half2_rn(v.x, v.y);
    __half2 h1 = __floats2half2_rn(v.z, v.w);
    return make_uint2(*(uint32_t*)&h0, *(uint32_t*)&h1);
}
__device__ __forceinline__ uint2 cvt_h4s(float4 v, float s) {
    return cvt_h4(make_float4(v.x * s, v.y * s, v.z * s, v.w * s));
}
__device__ __forceinline__ void split2(float a, float b, uint32_t& hw, uint32_t& lw) {
    __half2 h = __floats2half2_rn(a, b);
    float ra = a - __low2float(h), rb = b - __high2float(h);
    __half2 l = __floats2half2_rn(ra, rb);
    hw = *(uint32_t*)&h;
    lw = *(uint32_t*)&l;
}

// ---------------- tile slot layout per TERMS ----------------
template <int TERMS> struct Slots {
    static constexpr int SAh = 0;
    static constexpr int SAl = 1;
    static constexpr int SBh = (TERMS == 1) ? 1 : 2;
    static constexpr int SBl = 3;
    static constexpr int NT  = (TERMS == 1) ? 2 : (TERMS == 2) ? 3 : 4;
    static constexpr int BUF = NT * TILE_B;
};

// ---------------- compute one 32-deep K tile ----------------
template <int TERMS>
__device__ __forceinline__ void compute_kt(uint32_t bb, float acc[16][4],
                                           int a_off, int b_off, int wr, int wc) {
    using S = Slots<TERMS>;
#pragma unroll
    for (int ks = 0; ks < 2; ++ks) {
        const uint32_t koff = ks * 32;
        uint32_t bh[4][2], bl[4][2];
#pragma unroll
        for (int n2 = 0; n2 < 2; ++n2) {
            const uint32_t nbase = (wc * 32 + n2 * 16) * 80 + koff + b_off;
            uint32_t r4[4];
            ldmx4(r4, bb + S::SBh * TILE_B + nbase);
            bh[n2 * 2][0] = r4[0]; bh[n2 * 2][1] = r4[1];
            bh[n2 * 2 + 1][0] = r4[2]; bh[n2 * 2 + 1][1] = r4[3];
            if (TERMS == 3) {
                ldmx4(r4, bb + S::SBl * TILE_B + nbase);
                bl[n2 * 2][0] = r4[0]; bl[n2 * 2][1] = r4[1];
                bl[n2 * 2 + 1][0] = r4[2]; bl[n2 * 2 + 1][1] = r4[3];
            }
        }
#pragma unroll
        for (int mi = 0; mi < 4; ++mi) {
            const uint32_t mbase = (wr * 64 + mi * 16) * 80 + koff + a_off;
            uint32_t ah[4], al[4];
            ldmx4(ah, bb + S::SAh * TILE_B + mbase);
            if (TERMS >= 2) ldmx4(al, bb + S::SAl * TILE_B + mbase);
#pragma unroll
            for (int ni = 0; ni < 4; ++ni) {
                mma_f16(acc[mi * 4 + ni], ah, bh[ni]);
                if (TERMS >= 2) mma_f16(acc[mi * 4 + ni], al, bh[ni]);
                if (TERMS == 3) mma_f16(acc[mi * 4 + ni], ah, bl[ni]);
            }
        }
    }
}

// issue cp.async for one fp16 tile (2x16B chunks/thread)
__device__ __forceinline__ void issue_tile(uint32_t bb, int tile, const hf* base,
                                           int ld, int k0, int t) {
    int row = t >> 2, q = t & 3;
    cp16(bb + tile * TILE_B + row * 80 + q * 16, base + (size_t)row * ld + k0 + q * 8);
    row = (t + 256) >> 2; q = (t + 256) & 3;
    cp16(bb + tile * TILE_B + row * 80 + q * 16, base + (size_t)row * ld + k0 + q * 8);
}

// ---------------- pre-split fp16 core (TERMS = 1, 2 or 3) ----------------
template <int TERMS>
__device__ __forceinline__ void mm_f16_core(const hf* __restrict__ Ah,
                                            const hf* __restrict__ Al, int lda,
                                            const hf* __restrict__ Bh,
                                            const hf* __restrict__ Bl, int ldb,
                                            int ktiles, float acc[16][4]) {
    using S = Slots<TERMS>;
    extern __shared__ __align__(128) char dsm[];
    const int t = threadIdx.x, lane = t & 31, w = t >> 5;
    const int wr = w >> 2, wc = w & 3;
    const uint32_t sb = smem_u32(dsm);
    const int a_off = ((lane & 7) + ((lane >> 3) & 1) * 8) * 80 + ((lane >> 4) & 1) * 16;
    const int b_off = ((lane & 7) + ((lane >> 4) & 1) * 8) * 80 + ((lane >> 3) & 1) * 16;

#pragma unroll
    for (int i = 0; i < 16; ++i)
#pragma unroll
        for (int j = 0; j < 4; ++j) acc[i][j] = 0.0f;

    issue_tile(sb, S::SAh, Ah, lda, 0, t);
    if (TERMS >= 2) issue_tile(sb, S::SAl, Al, lda, 0, t);
    issue_tile(sb, S::SBh, Bh, ldb, 0, t);
    if (TERMS == 3) issue_tile(sb, S::SBl, Bl, ldb, 0, t);
    cp_commit();

    int cur = 0;
    for (int kt = 0; kt < ktiles; ++kt) {
        const bool more = (kt + 1 < ktiles);
        if (more) {
            const uint32_t nb = sb + (cur ^ 1) * S::BUF;
            const int k0 = (kt + 1) * KT;
            issue_tile(nb, S::SAh, Ah, lda, k0, t);
            if (TERMS >= 2) issue_tile(nb, S::SAl, Al, lda, k0, t);
            issue_tile(nb, S::SBh, Bh, ldb, k0, t);
            if (TERMS == 3) issue_tile(nb, S::SBl, Bl, ldb, k0, t);
            cp_commit();
            cp_wait<1>();
        } else {
            cp_wait<0>();
        }
        __syncthreads();
        compute_kt<TERMS>(sb + cur * S::BUF, acc, a_off, b_off, wr, wc);
        __syncthreads();
        cur ^= 1;
    }
}

// ---------------- A-fp32 core: single term, in-kernel cvt with scale ----------------
__device__ __forceinline__ void mm_a_core(const float* __restrict__ A, int lda,
                                          const hf* __restrict__ Bh, int ldb,
                                          int ktiles, float acc[16][4], float ascale) {
    using S = Slots<1>;
    extern __shared__ __align__(128) char dsm[];
    const int t = threadIdx.x, lane = t & 31, w = t >> 5;
    const int wr = w >> 2, wc = w & 3;
    const uint32_t sb = smem_u32(dsm);
    const int a_off = ((lane & 7) + ((lane >> 3) & 1) * 8) * 80 + ((lane >> 4) & 1) * 16;
    const int b_off = ((lane & 7) + ((lane >> 4) & 1) * 8) * 80 + ((lane >> 3) & 1) * 16;

#pragma unroll
    for (int i = 0; i < 16; ++i)
#pragma unroll
        for (int j = 0; j < 4; ++j) acc[i][j] = 0.0f;

    float4 av[4];
    issue_tile(sb, S::SBh, Bh, ldb, 0, t);
    cp_commit();
#pragma unroll
    for (int i = 0; i < 4; ++i) {
        const int idx = t + 256 * i, r = idx >> 3, c4 = (idx & 7) << 2;
        av[i] = *(const float4*)&A[(size_t)r * lda + c4];
    }
#pragma unroll
    for (int i = 0; i < 4; ++i) {
        const int idx = t + 256 * i, r = idx >> 3, c4 = (idx & 7) << 2;
        *(uint2*)(dsm + S::SAh * TILE_B + r * 80 + c4 * 2) = cvt_h4s(av[i], ascale);
    }

    int cur = 0;
    for (int kt = 0; kt < ktiles; ++kt) {
        const bool more = (kt + 1 < ktiles);
        if (more) {
#pragma unroll
            for (int i = 0; i < 4; ++i) {
                const int idx = t + 256 * i, r = idx >> 3, c4 = (idx & 7) << 2;
                av[i] = *(const float4*)&A[(size_t)r * lda + (kt + 1) * KT + c4];
            }
            issue_tile(sb + (cur ^ 1) * S::BUF, S::SBh, Bh, ldb, (kt + 1) * KT, t);
            cp_commit();
            cp_wait<1>();
        } else {
            cp_wait<0>();
        }
        __syncthreads();
        compute_kt<1>(sb + cur * S::BUF, acc, a_off, b_off, wr, wc);
        __syncthreads();
        if (more) {
#pragma unroll
            for (int i = 0; i < 4; ++i) {
                const int idx = t + 256 * i, r = idx >> 3, c4 = (idx & 7) << 2;
                *(uint2*)(dsm + (cur ^ 1) * S::BUF + S::SAh * TILE_B + r * 80 + c4 * 2) =
                    cvt_h4s(av[i], ascale);
            }
        }
        cur ^= 1;
    }
}

// ---------------- fused prep kernel ----------------
// blocks [0,16): H tensor   [16,1040): weights split + zero accumulators
// [1040,1552): wbases transpose->fp16   [1552,2064): bases ->fp16 (ILP 4)
#define HT_B0  0
#define WT_B0  16
#define TWB_B0 1040
#define TBS_B0 1552
__global__ void __launch_bounds__(256) prep_kernel(const float* __restrict__ Aop,
                                                   const float* __restrict__ Bop,
                                                   const float* __restrict__ Dout,
                                                   const float* __restrict__ Din,
                                                   const float* __restrict__ product,
                                                   const float* __restrict__ wgt,
                                                   const float* __restrict__ wb,
                                                   const float* __restrict__ bases) {
    __shared__ float sm[5120];   // 20 KB: ht Aj|Bj|Qs; twb tile[32][129]
    const int bid = blockIdx.x;
    const int t = threadIdx.x;

    if (bid < WT_B0) {
        // ---- H tensor ----
        const int j = bid;
        float* Aj = sm;
        float* Bj = sm + 512;
        float* Qs = sm + 1024;
        for (int i = t; i < NR * 64; i += 256) {
            Aj[i] = Aop[j * (NR * 64) + i];
            Bj[i] = Bop[j * (NR * 64) + i];
        }
        __syncthreads();
#pragma unroll
        for (int s = 0; s < 16; ++s) {
            int idx = t + 256 * s;
            int m = idx >> 6, n = idx & 63;
            float q = 0.0f;
#pragma unroll
            for (int r = 0; r < NR; ++r) q += Aj[r * 64 + m] * Bj[r * 64 + n];
            Qs[idx] = q;
        }
        __syncthreads();
#pragma unroll 4
        for (int s = 0; s < 64; ++s) {
            int idx = t + 256 * s;        // 16384 = 128x128
            int k = idx >> 7, l = idx & 127;
            float h = Dout[j * 128 + k] * Din[j * 128 + l] * product[k * 128 + l];
            if (k < 64 && l < 64) h += Qs[k * 64 + l];
            g_Hk_h[k * (NJ * 128) + j * 128 + l] = __float2half_rn(h);
        }
    } else if (bid < TWB_B0) {
        // ---- weights (hi only, scaled) + zero accumulators ----
        int id = (bid - WT_B0) * 256 + t;   // 262144
        g_xhatT[id] = 0.0f;
        g_y[id]     = 0.0f;
        int ii = id & 127;
        int o  = (id >> 7) & 127;
        int j  = id >> 14;
        g_Wt_h[id] = __float2half_rn(wgt[(ii * 128 + o) * NJ + j] * WSCALE);
    } else if (bid < TBS_B0) {
        // ---- wbases[NPTS][128] -> g_wbT_h[128][NPTS], 128x32 tiles ----
        const int bt = bid - TWB_B0;        // 0..511
        const int xb = (bt >> 2) * 128;
        const int kb = (bt & 3) * 32;
        const int q  = t & 7;               // float4 col group
#pragma unroll
        for (int p = 0; p < 4; ++p) {
            const int xr = p * 32 + (t >> 3);
            float4 v = *(const float4*)&wb[(size_t)(xb + xr) * 128 + kb + q * 4];
            sm[(q * 4 + 0) * 129 + xr] = v.x;
            sm[(q * 4 + 1) * 129 + xr] = v.y;
            sm[(q * 4 + 2) * 129 + xr] = v.z;
            sm[(q * 4 + 3) * 129 + xr] = v.w;
        }
        __syncthreads();
        const int kr = t >> 3;              // 0..31
        const int xq = (t & 7) * 16;
        const float* row = &sm[kr * 129 + xq];
        uint32_t pk[8];
#pragma unroll
        for (int m = 0; m < 8; ++m) {
            __half2 h = __floats2half2_rn(row[2 * m], row[2 * m + 1]);
            pk[m] = *(uint32_t*)&h;
        }
        hf* dst = &g_wbT_h[(size_t)(kb + kr) * NPTS + xb + xq];
        *(uint4*)dst       = make_uint4(pk[0], pk[1], pk[2], pk[3]);
        *(uint4*)(dst + 8) = make_uint4(pk[4], pk[5], pk[6], pk[7]);
    } else {
        // ---- bases -> fp16 elementwise, 4 float4/thread ----
        const int bt = bid - TBS_B0;        // 0..511
#pragma unroll
        for (int s = 0; s < 4; ++s) {
            int i4 = bt * 256 + t + s * 131072;
            float4 v = ((const float4*)bases)[i4];
            *(uint2*)&g_bs_h[(size_t)i4 * 4] = cvt_h4(v);
        }
    }
}

// xhatT fp32 -> fp16 hi
__global__ void __launch_bounds__(256) cvt0_kernel() {
    int i4 = blockIdx.x * 256 + threadIdx.x;   // 65536 float4s
    float4 v = ((const float4*)g_xhatT)[i4];
    *(uint2*)&g_xhT_h[(size_t)i4 * 4] = cvt_h4(v);
}

// ---------------- GEMM stage kernels ----------------
// stage A: xhatT[b][l][i] += x[(b,i),:] @ wbT  (16 b-blocks x 16 K-splits, 1-term)
__global__ void __launch_bounds__(256) k_mm_a(const float* __restrict__ x) {
    const int b  = blockIdx.x;
    const int ks = blockIdx.y;
    float acc[16][4];
    mm_a_core(x + (size_t)(b * 128) * NPTS + ks * 1024, NPTS,
              g_wbT_h + ks * 1024, NPTS, 32, acc, 1.0f);
    const int lane = threadIdx.x & 31, w = threadIdx.x >> 5;
    const int wr = w >> 2, wc = w & 3;
    float* dst = g_xhatT + (size_t)b * 16384;
#pragma unroll
    for (int mi = 0; mi < 4; ++mi)
#pragma unroll
        for (int ni = 0; ni < 4; ++ni) {
            const int row = wr * 64 + mi * 16 + (lane >> 2);   // i
            const int col = wc * 32 + ni * 8 + (lane & 3) * 2; // l
            const float* a = acc[mi * 4 + ni];
            atomicAdd(&dst[(col + 0) * 128 + row],     a[0]);
            atomicAdd(&dst[(col + 1) * 128 + row],     a[1]);
            atomicAdd(&dst[(col + 0) * 128 + row + 8], a[2]);
            atomicAdd(&dst[(col + 1) * 128 + row + 8], a[3]);
        }
}

// fused stage ZY: per (b,j): ztile = Wt_h[j] @ xhat_h[b] (1-term);
//                 y += ztile(hi/lo) @ Hk_h[j] (2-term)
// smem: [0, 40960) GEMM1/GEMM2 double buffers (Slots<1>);
//       [40960, +4*TILE_B) ztile HI K-tiles; [+4*TILE_B, +8*TILE_B) ztile LO
#define ZY_ZH   (2 * Slots<1>::BUF)            // 40960
#define ZY_ZL   (ZY_ZH + 4 * TILE_B)           // 81920
#define ZY_SMEM (ZY_ZL + 4 * TILE_B)           // 122880
__global__ void __launch_bounds__(256) k_mm_zy() {
    extern __shared__ __align__(128) char dsm[];
    const int b = blockIdx.x >> 4, j = blockIdx.x & 15;
    const int t = threadIdx.x, lane = t & 31, w = t >> 5;
    const int wr = w >> 2, wc = w & 3;
    const uint32_t sb = smem_u32(dsm);
    const int a_off = ((lane & 7) + ((lane >> 3) & 1) * 8) * 80 + ((lane >> 4) & 1) * 16;
    const int b_off = ((lane & 7) + ((lane >> 4) & 1) * 8) * 80 + ((lane >> 3) & 1) * 16;

    float acc[16][4];
    // ---- GEMM1: Wt_h[j] @ xhat_h[b] -> acc (o x l), 1-term ----
    mm_f16_core<1>(g_Wt_h + (size_t)j * 16384, (const hf*)nullptr, 128,
                   g_xhT_h + (size_t)b * 16384, (const hf*)nullptr, 128, 4, acc);

    // ---- store ztile to smem, K-tile-blocked (tile index = wc) ----
#pragma unroll
    for (int mi = 0; mi < 4; ++mi)
#pragma unroll
        for (int ni = 0; ni < 4; ++ni) {
            const int row = wr * 64 + mi * 16 + (lane >> 2);      // o
            const int tc  = (ni * 8 + (lane & 3) * 2) * 2;        // byte col within tile
            const uint32_t hoff = ZY_ZH + wc * TILE_B + row * 80 + tc;
            const uint32_t loff = ZY_ZL + wc * TILE_B + row * 80 + tc;
            const float* a = acc[mi * 4 + ni];
            uint32_t hw, lw;
            split2(a[0], a[1], hw, lw);
            *(uint32_t*)(dsm + hoff) = hw;
            *(uint32_t*)(dsm + loff) = lw;
            split2(a[2], a[3], hw, lw);
            *(uint32_t*)(dsm + hoff + 8 * 80) = hw;
            *(uint32_t*)(dsm + loff + 8 * 80) = lw;
        }

    // ---- GEMM2: ztile (hi/lo, resident) @ Hk_h[j] -> y ----
#pragma unroll
    for (int i = 0; i < 16; ++i)
#pragma unroll
        for (int q = 0; q < 4; ++q) acc[i][q] = 0.0f;

    const hf* Bh = g_Hk_h + j * 128;     // row k: stride 2048
    issue_tile(sb, 0, Bh, 2048, 0, t);
    cp_commit();

    int cur = 0;
    for (int kt = 0; kt < 4; ++kt) {
        const bool more = (kt + 1 < 4);
        if (more) {
            issue_tile(sb, cur ^ 1, Bh, 2048, (kt + 1) * KT, t);
            cp_commit();
            cp_wait<1>();
        } else {
            cp_wait<0>();
        }
        __syncthreads();     // covers ztile visibility (first iter) + B arrival
        const uint32_t bb = sb + cur * TILE_B;
        const uint32_t zh = sb + ZY_ZH + kt * TILE_B;
        const uint32_t zl = sb + ZY_ZL + kt * TILE_B;
#pragma unroll
        for (int ks = 0; ks < 2; ++ks) {
            const uint32_t koff = ks * 32;
            uint32_t bh4[4][2];
#pragma unroll
            for (int n2 = 0; n2 < 2; ++n2) {
                uint32_t r4[4];
                ldmx4(r4, bb + (wc * 32 + n2 * 16) * 80 + koff + b_off);
                bh4[n2 * 2][0] = r4[0]; bh4[n2 * 2][1] = r4[1];
                bh4[n2 * 2 + 1][0] = r4[2]; bh4[n2 * 2 + 1][1] = r4[3];
            }
#pragma unroll
            for (int mi = 0; mi < 4; ++mi) {
                const uint32_t mbase = (wr * 64 + mi * 16) * 80 + koff + a_off;
                uint32_t ah[4], al[4];
                ldmx4(ah, zh + mbase);
                ldmx4(al, zl + mbase);
#pragma unroll
                for (int ni = 0; ni < 4; ++ni) {
                    mma_f16(acc[mi * 4 + ni], ah, bh4[ni]);
                    mma_f16(acc[mi * 4 + ni], al, bh4[ni]);
                }
            }
        }
        __syncthreads();
        cur ^= 1;
    }

    // ---- epilogue: atomic accumulate into g_y ----
#pragma unroll
    for (int mi = 0; mi < 4; ++mi)
#pragma unroll
        for (int ni = 0; ni < 4; ++ni) {
            const int row = b * 128 + wr * 64 + mi * 16 + (lane >> 2);  // (b,o)
            const int col = wc * 32 + ni * 8 + (lane & 3) * 2;          // k
            const float* a = acc[mi * 4 + ni];
            atomicAdd(&g_y[(size_t)row * 128 + col],           a[0]);
            atomicAdd(&g_y[(size_t)row * 128 + col + 1],       a[1]);
            atomicAdd(&g_y[(size_t)(row + 8) * 128 + col],     a[2]);
            atomicAdd(&g_y[(size_t)(row + 8) * 128 + col + 1], a[3]);
        }
}

// stage D: out = (y * 2^-14, cvt fp16 in-kernel) @ bases_h^T (1-term)
__global__ void __launch_bounds__(256) k_mm_d(float* __restrict__ out) {
    const int row0 = blockIdx.x * 128;
    const int x0   = blockIdx.y * 128;
    float acc[16][4];
    mm_a_core(g_y + (size_t)row0 * 128, 128,
              g_bs_h + (size_t)x0 * 128, 128, 4, acc, WINV);
    const int lane = threadIdx.x & 31, w = threadIdx.x >> 5;
    const int wr = w >> 2, wc = w & 3;
#pragma unroll
    for (int mi = 0; mi < 4; ++mi)
#pragma unroll
        for (int ni = 0; ni < 4; ++ni) {
            const int row = row0 + wr * 64 + mi * 16 + (lane >> 2);
            const int col = x0 + wc * 32 + ni * 8 + (lane & 3) * 2;
            const float* a = acc[mi * 4 + ni];
            *(float2*)&out[(size_t)row * NPTS + col]       = make_float2(a[0], a[1]);
            *(float2*)&out[(size_t)(row + 8) * NPTS + col] = make_float2(a[2], a[3]);
        }
}

// ---------------- launch ----------------
extern "C" void kernel_launch(void* const* d_in, const int* in_sizes, int n_in,
                              void* d_out, int out_size) {
    const float* x       = (const float*)d_in[0];
    const float* bases   = (const float*)d_in[1];
    const float* wbases  = (const float*)d_in[2];
    const float* product = (const float*)d_in[3];
    const float* Dout    = (const float*)d_in[4];
    const float* Din     = (const float*)d_in[5];
    const float* Aop     = (const float*)d_in[6];
    const float* Bop     = (const float*)d_in[7];
    const float* weights = (const float*)d_in[8];
    float* out = (float*)d_out;

    const int SM_1 = 2 * Slots<1>::BUF;   // 40960
    cudaFuncSetAttribute(k_mm_a,  cudaFuncAttributeMaxDynamicSharedMemorySize, SM_1);
    cudaFuncSetAttribute(k_mm_zy, cudaFuncAttributeMaxDynamicSharedMemorySize, ZY_SMEM);
    cudaFuncSetAttribute(k_mm_d,  cudaFuncAttributeMaxDynamicSharedMemorySize, SM_1);

    prep_kernel<<<2064, 256>>>(Aop, Bop, Dout, Din, product, weights, wbases, bases);
    k_mm_a<<<dim3(16, 16), 256, SM_1>>>(x);
    cvt0_kernel<<<256, 256>>>();
    k_mm_zy<<<NB * NJ, 256, ZY_SMEM>>>();
    k_mm_d<<<dim3(16, 128), 256, SM_1>>>(out);
}

// round 15
// speedup vs baseline: 1.8057x; 1.0710x over previous
#include <cuda_runtime.h>
#include <cuda_fp16.h>
#include <cstdint>

#define NB    16
#define NDIM  128
#define NPTS  16384
#define NJ    16
#define NR    8
#define KT    32                     // K-tile depth
#define TILE_B (128 * 40 * 2)        // 10240 bytes per fp16 tile (80B rows)
#define WSCALE 16384.0f
#define WINV   (1.0f / 16384.0f)

typedef __half hf;

// ---------------- device scratch ----------------
__device__ __align__(16) float g_xhatT[NB * 128 * 128];      // [b][l][i]  1 MB
__device__ __align__(16) float g_y    [NB * 128 * 128];      // [(b,o)][k] 1 MB (scaled 2^14)
__device__ __align__(16) hf g_xhT_h[NB * 128 * 128];         // [b][l][i]
__device__ __align__(16) hf g_Wt_h [NJ * 128 * 128];         // [j][o][i] (x 2^14)
__device__ __align__(16) hf g_Hk_h [128 * NJ * 128];         // [k][(j,l)]
__device__ __align__(16) hf g_y_h  [2048 * 128];             // descaled fp16
__device__ __align__(16) hf g_wbT_h[128 * NPTS];             // [l][x]
__device__ __align__(16) hf g_bs_h [NPTS * 128];             // [x][k]

// ---------------- helpers ----------------
__device__ __forceinline__ uint32_t smem_u32(const void* p) {
    uint32_t a;
    asm("{ .reg .u64 t; cvta.to.shared.u64 t, %1; cvt.u32.u64 %0, t; }" : "=r"(a) : "l"(p));
    return a;
}
__device__ __forceinline__ void cp16(uint32_t dst, const void* src) {
    asm volatile("cp.async.cg.shared.global [%0], [%1], 16;" :: "r"(dst), "l"(src));
}
__device__ __forceinline__ void cp_commit() {
    asm volatile("cp.async.commit_group;" ::: "memory");
}
template <int N>
__device__ __forceinline__ void cp_wait() {
    asm volatile("cp.async.wait_group %0;" :: "n"(N) : "memory");
}
__device__ __forceinline__ void ldmx4(uint32_t* r, uint32_t addr) {
    asm volatile("ldmatrix.sync.aligned.m8n8.x4.shared.b16 {%0,%1,%2,%3}, [%4];"
                 : "=r"(r[0]), "=r"(r[1]), "=r"(r[2]), "=r"(r[3]) : "r"(addr));
}
__device__ __forceinline__ void mma_f16(float* c, const uint32_t* a, const uint32_t* b) {
    asm volatile("mma.sync.aligned.m16n8k16.row.col.f32.f16.f16.f32 "
                 "{%0,%1,%2,%3}, {%4,%5,%6,%7}, {%8,%9}, {%0,%1,%2,%3};"
                 : "+f"(c[0]), "+f"(c[1]), "+f"(c[2]), "+f"(c[3])
                 : "r"(a[0]), "r"(a[1]), "r"(a[2]), "r"(a[3]), "r"(b[0]), "r"(b[1]));
}
__device__ __forceinline__ uint2 cvt_h4(float4 v) {
    __half2 h0 = __floats2half2_rn(v.x, v.y);
    __half2 h1 = __floats2half2_rn(v.z, v.w);
    return make_uint2(*(uint32_t*)&h0, *(uint32_t*)&h1);
}
__device__ __forceinline__ uint2 cvt_h4s(float4 v, float s) {
    return cvt_h4(make_float4(v.x * s, v.y * s, v.z * s, v.w * s));
}

// ---------------- tile slot layout per TERMS ----------------
template <int TERMS> struct Slots {
    static constexpr int SAh = 0;
    static constexpr int SAl = 1;
    static constexpr int SBh = (TERMS == 1) ? 1 : 2;
    static constexpr int SBl = 3;
    static constexpr int NT  = (TERMS == 1) ? 2 : (TERMS == 2) ? 3 : 4;
    static constexpr int BUF = NT * TILE_B;
};

// ---------------- compute one 32-deep K tile ----------------
template <int TERMS>
__device__ __forceinline__ void compute_kt(uint32_t bb, float acc[16][4],
                                           int a_off, int b_off, int wr, int wc) {
    using S = Slots<TERMS>;
#pragma unroll
    for (int ks = 0; ks < 2; ++ks) {
        const uint32_t koff = ks * 32;
        uint32_t bh[4][2], bl[4][2];
#pragma unroll
        for (int n2 = 0; n2 < 2; ++n2) {
            const uint32_t nbase = (wc * 32 + n2 * 16) * 80 + koff + b_off;
            uint32_t r4[4];
            ldmx4(r4, bb + S::SBh * TILE_B + nbase);
            bh[n2 * 2][0] = r4[0]; bh[n2 * 2][1] = r4[1];
            bh[n2 * 2 + 1][0] = r4[2]; bh[n2 * 2 + 1][1] = r4[3];
            if (TERMS == 3) {
                ldmx4(r4, bb + S::SBl * TILE_B + nbase);
                bl[n2 * 2][0] = r4[0]; bl[n2 * 2][1] = r4[1];
                bl[n2 * 2 + 1][0] = r4[2]; bl[n2 * 2 + 1][1] = r4[3];
            }
        }
#pragma unroll
        for (int mi = 0; mi < 4; ++mi) {
            const uint32_t mbase = (wr * 64 + mi * 16) * 80 + koff + a_off;
            uint32_t ah[4], al[4];
            ldmx4(ah, bb + S::SAh * TILE_B + mbase);
            if (TERMS >= 2) ldmx4(al, bb + S::SAl * TILE_B + mbase);
#pragma unroll
            for (int ni = 0; ni < 4; ++ni) {
                mma_f16(acc[mi * 4 + ni], ah, bh[ni]);
                if (TERMS >= 2) mma_f16(acc[mi * 4 + ni], al, bh[ni]);
                if (TERMS == 3) mma_f16(acc[mi * 4 + ni], ah, bl[ni]);
            }
        }
    }
}

// issue cp.async for one fp16 tile (2x16B chunks/thread)
__device__ __forceinline__ void issue_tile(uint32_t bb, int tile, const hf* base,
                                           int ld, int k0, int t) {
    int row = t >> 2, q = t & 3;
    cp16(bb + tile * TILE_B + row * 80 + q * 16, base + (size_t)row * ld + k0 + q * 8);
    row = (t + 256) >> 2; q = (t + 256) & 3;
    cp16(bb + tile * TILE_B + row * 80 + q * 16, base + (size_t)row * ld + k0 + q * 8);
}

// ---------------- pre-split fp16 core (TERMS = 1, 2 or 3) ----------------
template <int TERMS>
__device__ __forceinline__ void mm_f16_core(const hf* __restrict__ Ah,
                                            const hf* __restrict__ Al, int lda,
                                            const hf* __restrict__ Bh,
                                            const hf* __restrict__ Bl, int ldb,
                                            int ktiles, float acc[16][4]) {
    using S = Slots<TERMS>;
    extern __shared__ __align__(128) char dsm[];
    const int t = threadIdx.x, lane = t & 31, w = t >> 5;
    const int wr = w >> 2, wc = w & 3;
    const uint32_t sb = smem_u32(dsm);
    const int a_off = ((lane & 7) + ((lane >> 3) & 1) * 8) * 80 + ((lane >> 4) & 1) * 16;
    const int b_off = ((lane & 7) + ((lane >> 4) & 1) * 8) * 80 + ((lane >> 3) & 1) * 16;

#pragma unroll
    for (int i = 0; i < 16; ++i)
#pragma unroll
        for (int j = 0; j < 4; ++j) acc[i][j] = 0.0f;

    issue_tile(sb, S::SAh, Ah, lda, 0, t);
    if (TERMS >= 2) issue_tile(sb, S::SAl, Al, lda, 0, t);
    issue_tile(sb, S::SBh, Bh, ldb, 0, t);
    if (TERMS == 3) issue_tile(sb, S::SBl, Bl, ldb, 0, t);
    cp_commit();

    int cur = 0;
    for (int kt = 0; kt < ktiles; ++kt) {
        const bool more = (kt + 1 < ktiles);
        if (more) {
            const uint32_t nb = sb + (cur ^ 1) * S::BUF;
            const int k0 = (kt + 1) * KT;
            issue_tile(nb, S::SAh, Ah, lda, k0, t);
            if (TERMS >= 2) issue_tile(nb, S::SAl, Al, lda, k0, t);
            issue_tile(nb, S::SBh, Bh, ldb, k0, t);
            if (TERMS == 3) issue_tile(nb, S::SBl, Bl, ldb, k0, t);
            cp_commit();
            cp_wait<1>();
        } else {
            cp_wait<0>();
        }
        __syncthreads();
        compute_kt<TERMS>(sb + cur * S::BUF, acc, a_off, b_off, wr, wc);
        __syncthreads();
        cur ^= 1;
    }
}

// ---------------- A-fp32 core: single term, in-kernel cvt with scale ----------------
__device__ __forceinline__ void mm_a_core(const float* __restrict__ A, int lda,
                                          const hf* __restrict__ Bh, int ldb,
                                          int ktiles, float acc[16][4], float ascale) {
    using S = Slots<1>;
    extern __shared__ __align__(128) char dsm[];
    const int t = threadIdx.x, lane = t & 31, w = t >> 5;
    const int wr = w >> 2, wc = w & 3;
    const uint32_t sb = smem_u32(dsm);
    const int a_off = ((lane & 7) + ((lane >> 3) & 1) * 8) * 80 + ((lane >> 4) & 1) * 16;
    const int b_off = ((lane & 7) + ((lane >> 4) & 1) * 8) * 80 + ((lane >> 3) & 1) * 16;

#pragma unroll
    for (int i = 0; i < 16; ++i)
#pragma unroll
        for (int j = 0; j < 4; ++j) acc[i][j] = 0.0f;

    float4 av[4];
    issue_tile(sb, S::SBh, Bh, ldb, 0, t);
    cp_commit();
#pragma unroll
    for (int i = 0; i < 4; ++i) {
        const int idx = t + 256 * i, r = idx >> 3, c4 = (idx & 7) << 2;
        av[i] = *(const float4*)&A[(size_t)r * lda + c4];
    }
#pragma unroll
    for (int i = 0; i < 4; ++i) {
        const int idx = t + 256 * i, r = idx >> 3, c4 = (idx & 7) << 2;
        *(uint2*)(dsm + S::SAh * TILE_B + r * 80 + c4 * 2) = cvt_h4s(av[i], ascale);
    }

    int cur = 0;
    for (int kt = 0; kt < ktiles; ++kt) {
        const bool more = (kt + 1 < ktiles);
        if (more) {
#pragma unroll
            for (int i = 0; i < 4; ++i) {
                const int idx = t + 256 * i, r = idx >> 3, c4 = (idx & 7) << 2;
                av[i] = *(const float4*)&A[(size_t)r * lda + (kt + 1) * KT + c4];
            }
            issue_tile(sb + (cur ^ 1) * S::BUF, S::SBh, Bh, ldb, (kt + 1) * KT, t);
            cp_commit();
            cp_wait<1>();
        } else {
            cp_wait<0>();
        }
        __syncthreads();
        compute_kt<1>(sb + cur * S::BUF, acc, a_off, b_off, wr, wc);
        __syncthreads();
        if (more) {
#pragma unroll
            for (int i = 0; i < 4; ++i) {
                const int idx = t + 256 * i, r = idx >> 3, c4 = (idx & 7) << 2;
                *(uint2*)(dsm + (cur ^ 1) * S::BUF + S::SAh * TILE_B + r * 80 + c4 * 2) =
                    cvt_h4s(av[i], ascale);
            }
        }
        cur ^= 1;
    }
}

// ---------------- fused prep kernel ----------------
// blocks [0,16): H tensor   [16,1040): weights split + zero accumulators
// [1040,1552): wbases transpose->fp16   [1552,2064): bases ->fp16 (ILP 4)
#define WT_B0  16
#define TWB_B0 1040
#define TBS_B0 1552
__global__ void __launch_bounds__(256) prep_kernel(const float* __restrict__ Aop,
                                                   const float* __restrict__ Bop,
                                                   const float* __restrict__ Dout,
                                                   const float* __restrict__ Din,
                                                   const float* __restrict__ product,
                                                   const float* __restrict__ wgt,
                                                   const float* __restrict__ wb,
                                                   const float* __restrict__ bases) {
    __shared__ float sm[5120];   // 20 KB: ht Aj|Bj|Qs; twb tile[32][129]
    const int bid = blockIdx.x;
    const int t = threadIdx.x;

    if (bid < WT_B0) {
        // ---- H tensor ----
        const int j = bid;
        float* Aj = sm;
        float* Bj = sm + 512;
        float* Qs = sm + 1024;
        for (int i = t; i < NR * 64; i += 256) {
            Aj[i] = Aop[j * (NR * 64) + i];
            Bj[i] = Bop[j * (NR * 64) + i];
        }
        __syncthreads();
#pragma unroll
        for (int s = 0; s < 16; ++s) {
            int idx = t + 256 * s;
            int m = idx >> 6, n = idx & 63;
            float q = 0.0f;
#pragma unroll
            for (int r = 0; r < NR; ++r) q += Aj[r * 64 + m] * Bj[r * 64 + n];
            Qs[idx] = q;
        }
        __syncthreads();
#pragma unroll 4
        for (int s = 0; s < 64; ++s) {
            int idx = t + 256 * s;        // 16384 = 128x128
            int k = idx >> 7, l = idx & 127;
            float h = Dout[j * 128 + k] * Din[j * 128 + l] * product[k * 128 + l];
            if (k < 64 && l < 64) h += Qs[k * 64 + l];
            g_Hk_h[k * (NJ * 128) + j * 128 + l] = __float2half_rn(h);
        }
    } else if (bid < TWB_B0) {
        // ---- weights (hi only, scaled) + zero accumulators ----
        int id = (bid - WT_B0) * 256 + t;   // 262144
        g_xhatT[id] = 0.0f;
        g_y[id]     = 0.0f;
        int ii = id & 127;
        int o  = (id >> 7) & 127;
        int j  = id >> 14;
        g_Wt_h[id] = __float2half_rn(wgt[(ii * 128 + o) * NJ + j] * WSCALE);
    } else if (bid < TBS_B0) {
        // ---- wbases[NPTS][128] -> g_wbT_h[128][NPTS], 128x32 tiles ----
        const int bt = bid - TWB_B0;        // 0..511
        const int xb = (bt >> 2) * 128;
        const int kb = (bt & 3) * 32;
        const int q  = t & 7;               // float4 col group
#pragma unroll
        for (int p = 0; p < 4; ++p) {
            const int xr = p * 32 + (t >> 3);
            float4 v = *(const float4*)&wb[(size_t)(xb + xr) * 128 + kb + q * 4];
            sm[(q * 4 + 0) * 129 + xr] = v.x;
            sm[(q * 4 + 1) * 129 + xr] = v.y;
            sm[(q * 4 + 2) * 129 + xr] = v.z;
            sm[(q * 4 + 3) * 129 + xr] = v.w;
        }
        __syncthreads();
        const int kr = t >> 3;              // 0..31
        const int xq = (t & 7) * 16;
        const float* row = &sm[kr * 129 + xq];
        uint32_t pk[8];
#pragma unroll
        for (int m = 0; m < 8; ++m) {
            __half2 h = __floats2half2_rn(row[2 * m], row[2 * m + 1]);
            pk[m] = *(uint32_t*)&h;
        }
        hf* dst = &g_wbT_h[(size_t)(kb + kr) * NPTS + xb + xq];
        *(uint4*)dst       = make_uint4(pk[0], pk[1], pk[2], pk[3]);
        *(uint4*)(dst + 8) = make_uint4(pk[4], pk[5], pk[6], pk[7]);
    } else {
        // ---- bases -> fp16 elementwise, 4 float4/thread ----
        const int bt = bid - TBS_B0;        // 0..511
#pragma unroll
        for (int s = 0; s < 4; ++s) {
            int i4 = bt * 256 + t + s * 131072;
            float4 v = ((const float4*)bases)[i4];
            *(uint2*)&g_bs_h[(size_t)i4 * 4] = cvt_h4(v);
        }
    }
}

// xhatT fp32 -> fp16 hi
__global__ void __launch_bounds__(256) cvt0_kernel() {
    int i4 = blockIdx.x * 256 + threadIdx.x;   // 65536 float4s
    float4 v = ((const float4*)g_xhatT)[i4];
    *(uint2*)&g_xhT_h[(size_t)i4 * 4] = cvt_h4(v);
}

// y fp32 (scaled) -> fp16 descaled
__global__ void __launch_bounds__(256) cvty_kernel() {
    int i4 = blockIdx.x * 256 + threadIdx.x;   // 65536 float4s
    float4 v = ((const float4*)g_y)[i4];
    *(uint2*)&g_y_h[(size_t)i4 * 4] = cvt_h4s(v, WINV);
}

// ---------------- GEMM stage kernels ----------------
// stage A: xhatT[b][l][i] += x[(b,i),:] @ wbT  (16 b-blocks x 16 K-splits, 1-term)
__global__ void __launch_bounds__(256) k_mm_a(const float* __restrict__ x) {
    const int b  = blockIdx.x;
    const int ks = blockIdx.y;
    float acc[16][4];
    mm_a_core(x + (size_t)(b * 128) * NPTS + ks * 1024, NPTS,
              g_wbT_h + ks * 1024, NPTS, 32, acc, 1.0f);
    const int lane = threadIdx.x & 31, w = threadIdx.x >> 5;
    const int wr = w >> 2, wc = w & 3;
    float* dst = g_xhatT + (size_t)b * 16384;
#pragma unroll
    for (int mi = 0; mi < 4; ++mi)
#pragma unroll
        for (int ni = 0; ni < 4; ++ni) {
            const int row = wr * 64 + mi * 16 + (lane >> 2);   // i
            const int col = wc * 32 + ni * 8 + (lane & 3) * 2; // l
            const float* a = acc[mi * 4 + ni];
            atomicAdd(&dst[(col + 0) * 128 + row],     a[0]);
            atomicAdd(&dst[(col + 1) * 128 + row],     a[1]);
            atomicAdd(&dst[(col + 0) * 128 + row + 8], a[2]);
            atomicAdd(&dst[(col + 1) * 128 + row + 8], a[3]);
        }
}

// fused stage ZY: per (b,j): ztile = Wt_h[j] @ xhat_h[b] (1-term, fp16 in smem);
//                 y += ztile @ Hk_h[j] (1-term)
// smem: [0, 40960) double buffers (Slots<1>); [40960, +4*TILE_B) ztile HI K-tiles
#define ZY_ZH   (2 * Slots<1>::BUF)            // 40960
#define ZY_SMEM (ZY_ZH + 4 * TILE_B)           // 81920 -> 2 CTAs/SM
__global__ void __launch_bounds__(256, 2) k_mm_zy() {
    extern __shared__ __align__(128) char dsm[];
    const int b = blockIdx.x >> 4, j = blockIdx.x & 15;
    const int t = threadIdx.x, lane = t & 31, w = t >> 5;
    const int wr = w >> 2, wc = w & 3;
    const uint32_t sb = smem_u32(dsm);
    const int a_off = ((lane & 7) + ((lane >> 3) & 1) * 8) * 80 + ((lane >> 4) & 1) * 16;
    const int b_off = ((lane & 7) + ((lane >> 4) & 1) * 8) * 80 + ((lane >> 3) & 1) * 16;

    float acc[16][4];
    // ---- GEMM1: Wt_h[j] @ xhat_h[b] -> acc (o x l), 1-term ----
    mm_f16_core<1>(g_Wt_h + (size_t)j * 16384, (const hf*)nullptr, 128,
                   g_xhT_h + (size_t)b * 16384, (const hf*)nullptr, 128, 4, acc);

    // ---- store ztile (hi only) to smem, K-tile-blocked (tile index = wc) ----
#pragma unroll
    for (int mi = 0; mi < 4; ++mi)
#pragma unroll
        for (int ni = 0; ni < 4; ++ni) {
            const int row = wr * 64 + mi * 16 + (lane >> 2);      // o
            const int tc  = (ni * 8 + (lane & 3) * 2) * 2;        // byte col within tile
            const uint32_t hoff = ZY_ZH + wc * TILE_B + row * 80 + tc;
            const float* a = acc[mi * 4 + ni];
            __half2 h0 = __floats2half2_rn(a[0], a[1]);
            __half2 h1 = __floats2half2_rn(a[2], a[3]);
            *(uint32_t*)(dsm + hoff)          = *(uint32_t*)&h0;
            *(uint32_t*)(dsm + hoff + 8 * 80) = *(uint32_t*)&h1;
        }

    // ---- GEMM2: ztile (resident) @ Hk_h[j] -> y, 1-term ----
#pragma unroll
    for (int i = 0; i < 16; ++i)
#pragma unroll
        for (int q = 0; q < 4; ++q) acc[i][q] = 0.0f;

    const hf* Bh = g_Hk_h + j * 128;     // row k: stride 2048
    issue_tile(sb, 0, Bh, 2048, 0, t);
    cp_commit();

    int cur = 0;
    for (int kt = 0; kt < 4; ++kt) {
        const bool more = (kt + 1 < 4);
        if (more) {
            issue_tile(sb, cur ^ 1, Bh, 2048, (kt + 1) * KT, t);
            cp_commit();
            cp_wait<1>();
        } else {
            cp_wait<0>();
        }
        __syncthreads();     // covers ztile visibility (first iter) + B arrival
        const uint32_t bb = sb + cur * TILE_B;
        const uint32_t zh = sb + ZY_ZH + kt * TILE_B;
#pragma unroll
        for (int ks = 0; ks < 2; ++ks) {
            const uint32_t koff = ks * 32;
            uint32_t bh4[4][2];
#pragma unroll
            for (int n2 = 0; n2 < 2; ++n2) {
                uint32_t r4[4];
                ldmx4(r4, bb + (wc * 32 + n2 * 16) * 80 + koff + b_off);
                bh4[n2 * 2][0] = r4[0]; bh4[n2 * 2][1] = r4[1];
                bh4[n2 * 2 + 1][0] = r4[2]; bh4[n2 * 2 + 1][1] = r4[3];
            }
#pragma unroll
            for (int mi = 0; mi < 4; ++mi) {
                const uint32_t mbase = (wr * 64 + mi * 16) * 80 + koff + a_off;
                uint32_t ah[4];
                ldmx4(ah, zh + mbase);
#pragma unroll
                for (int ni = 0; ni < 4; ++ni)
                    mma_f16(acc[mi * 4 + ni], ah, bh4[ni]);
            }
        }
        __syncthreads();
        cur ^= 1;
    }

    // ---- epilogue: atomic accumulate into g_y ----
#pragma unroll
    for (int mi = 0; mi < 4; ++mi)
#pragma unroll
        for (int ni = 0; ni < 4; ++ni) {
            const int row = b * 128 + wr * 64 + mi * 16 + (lane >> 2);  // (b,o)
            const int col = wc * 32 + ni * 8 + (lane & 3) * 2;          // k
            const float* a = acc[mi * 4 + ni];
            atomicAdd(&g_y[(size_t)row * 128 + col],           a[0]);
            atomicAdd(&g_y[(size_t)row * 128 + col + 1],       a[1]);
            atomicAdd(&g_y[(size_t)(row + 8) * 128 + col],     a[2]);
            atomicAdd(&g_y[(size_t)(row + 8) * 128 + col + 1], a[3]);
        }
}

// stage D: out = y_h @ bases_h^T (1-term, all-cp.async pipeline)
__global__ void __launch_bounds__(256) k_mm_d(float* __restrict__ out) {
    const int row0 = blockIdx.x * 128;
    const int x0   = blockIdx.y * 128;
    float acc[16][4];
    mm_f16_core<1>(g_y_h + (size_t)row0 * 128, (const hf*)nullptr, 128,
                   g_bs_h + (size_t)x0 * 128, (const hf*)nullptr, 128, 4, acc);
    const int lane = threadIdx.x & 31, w = threadIdx.x >> 5;
    const int wr = w >> 2, wc = w & 3;
#pragma unroll
    for (int mi = 0; mi < 4; ++mi)
#pragma unroll
        for (int ni = 0; ni < 4; ++ni) {
            const int row = row0 + wr * 64 + mi * 16 + (lane >> 2);
            const int col = x0 + wc * 32 + ni * 8 + (lane & 3) * 2;
            const float* a = acc[mi * 4 + ni];
            *(float2*)&out[(size_t)row * NPTS + col]       = make_float2(a[0], a[1]);
            *(float2*)&out[(size_t)(row + 8) * NPTS + col] = make_float2(a[2], a[3]);
        }
}

// ---------------- launch ----------------
extern "C" void kernel_launch(void* const* d_in, const int* in_sizes, int n_in,
                              void* d_out, int out_size) {
    const float* x       = (const float*)d_in[0];
    const float* bases   = (const float*)d_in[1];
    const float* wbases  = (const float*)d_in[2];
    const float* product = (const float*)d_in[3];
    const float* Dout    = (const float*)d_in[4];
    const float* Din     = (const float*)d_in[5];
    const float* Aop     = (const float*)d_in[6];
    const float* Bop     = (const float*)d_in[7];
    const float* weights = (const float*)d_in[8];
    float* out = (float*)d_out;

    const int SM_1 = 2 * Slots<1>::BUF;   // 40960
    cudaFuncSetAttribute(k_mm_a,  cudaFuncAttributeMaxDynamicSharedMemorySize, SM_1);
    cudaFuncSetAttribute(k_mm_zy, cudaFuncAttributeMaxDynamicSharedMemorySize, ZY_SMEM);
    cudaFuncSetAttribute(k_mm_d,  cudaFuncAttributeMaxDynamicSharedMemorySize, SM_1);

    prep_kernel<<<2064, 256>>>(Aop, Bop, Dout, Din, product, weights, wbases, bases);
    k_mm_a<<<dim3(16, 16), 256, SM_1>>>(x);
    cvt0_kernel<<<256, 256>>>();
    k_mm_zy<<<NB * NJ, 256, ZY_SMEM>>>();
    cvty_kernel<<<256, 256>>>();
    k_mm_d<<<dim3(16, 128), 256, SM_1>>>(out);
}

// round 16
// speedup vs baseline: 1.8140x; 1.0046x over previous
#include <cuda_runtime.h>
#include <cuda_fp16.h>
#include <cstdint>

#define NB    16
#define NDIM  128
#define NPTS  16384
#define NJ    16
#define NR    8
#define KT    32                     // K-tile depth
#define TILE_B (128 * 40 * 2)        // 10240 bytes per fp16 tile (80B rows)
#define WSCALE 16384.0f
#define WINV   (1.0f / 16384.0f)

typedef __half hf;

// ---------------- device scratch ----------------
__device__ __align__(16) float g_xhatT[NB * 128 * 128];      // [b][l][i]  1 MB
__device__ __align__(16) float g_y    [NB * 128 * 128];      // [(b,o)][k] 1 MB (scaled 2^14)
__device__ __align__(16) hf g_xhT_h[NB * 128 * 128];         // [b][l][i]
__device__ __align__(16) hf g_Wt_h [NJ * 128 * 128];         // [j][o][i] (x 2^14)
__device__ __align__(16) hf g_Hk_h [128 * NJ * 128];         // [k][(j,l)]
__device__ __align__(16) hf g_y_h  [2048 * 128];             // descaled fp16
__device__ __align__(16) hf g_wbT_h[128 * NPTS];             // [l][x]
__device__ __align__(16) hf g_bs_h [NPTS * 128];             // [x][k]

// ---------------- helpers ----------------
__device__ __forceinline__ uint32_t smem_u32(const void* p) {
    uint32_t a;
    asm("{ .reg .u64 t; cvta.to.shared.u64 t, %1; cvt.u32.u64 %0, t; }" : "=r"(a) : "l"(p));
    return a;
}
__device__ __forceinline__ void cp16(uint32_t dst, const void* src) {
    asm volatile("cp.async.cg.shared.global [%0], [%1], 16;" :: "r"(dst), "l"(src));
}
__device__ __forceinline__ void cp_commit() {
    asm volatile("cp.async.commit_group;" ::: "memory");
}
template <int N>
__device__ __forceinline__ void cp_wait() {
    asm volatile("cp.async.wait_group %0;" :: "n"(N) : "memory");
}
__device__ __forceinline__ void ldmx4(uint32_t* r, uint32_t addr) {
    asm volatile("ldmatrix.sync.aligned.m8n8.x4.shared.b16 {%0,%1,%2,%3}, [%4];"
                 : "=r"(r[0]), "=r"(r[1]), "=r"(r[2]), "=r"(r[3]) : "r"(addr));
}
__device__ __forceinline__ void mma_f16(float* c, const uint32_t* a, const uint32_t* b) {
    asm volatile("mma.sync.aligned.m16n8k16.row.col.f32.f16.f16.f32 "
                 "{%0,%1,%2,%3}, {%4,%5,%6,%7}, {%8,%9}, {%0,%1,%2,%3};"
                 : "+f"(c[0]), "+f"(c[1]), "+f"(c[2]), "+f"(c[3])
                 : "r"(a[0]), "r"(a[1]), "r"(a[2]), "r"(a[3]), "r"(b[0]), "r"(b[1]));
}
__device__ __forceinline__ uint2 cvt_h4(float4 v) {
    __half2 h0 = __floats2half2_rn(v.x, v.y);
    __half2 h1 = __floats2half2_rn(v.z, v.w);
    return make_uint2(*(uint32_t*)&h0, *(uint32_t*)&h1);
}
__device__ __forceinline__ uint2 cvt_h4s(float4 v, float s) {
    return cvt_h4(make_float4(v.x * s, v.y * s, v.z * s, v.w * s));
}

// ---------------- tile slot layout per TERMS (streaming cores) ----------------
template <int TERMS> struct Slots {
    static constexpr int SAh = 0;
    static constexpr int SAl = 1;
    static constexpr int SBh = (TERMS == 1) ? 1 : 2;
    static constexpr int SBl = 3;
    static constexpr int NT  = (TERMS == 1) ? 2 : (TERMS == 2) ? 3 : 4;
    static constexpr int BUF = NT * TILE_B;
};

// ---------------- compute one 32-deep K tile (A at bb+0, B at bb+TILE_B for TERMS=1) --
template <int TERMS>
__device__ __forceinline__ void compute_kt(uint32_t bb, float acc[16][4],
                                           int a_off, int b_off, int wr, int wc) {
    using S = Slots<TERMS>;
#pragma unroll
    for (int ks = 0; ks < 2; ++ks) {
        const uint32_t koff = ks * 32;
        uint32_t bh[4][2], bl[4][2];
#pragma unroll
        for (int n2 = 0; n2 < 2; ++n2) {
            const uint32_t nbase = (wc * 32 + n2 * 16) * 80 + koff + b_off;
            uint32_t r4[4];
            ldmx4(r4, bb + S::SBh * TILE_B + nbase);
            bh[n2 * 2][0] = r4[0]; bh[n2 * 2][1] = r4[1];
            bh[n2 * 2 + 1][0] = r4[2]; bh[n2 * 2 + 1][1] = r4[3];
            if (TERMS == 3) {
                ldmx4(r4, bb + S::SBl * TILE_B + nbase);
                bl[n2 * 2][0] = r4[0]; bl[n2 * 2][1] = r4[1];
                bl[n2 * 2 + 1][0] = r4[2]; bl[n2 * 2 + 1][1] = r4[3];
            }
        }
#pragma unroll
        for (int mi = 0; mi < 4; ++mi) {
            const uint32_t mbase = (wr * 64 + mi * 16) * 80 + koff + a_off;
            uint32_t ah[4], al[4];
            ldmx4(ah, bb + S::SAh * TILE_B + mbase);
            if (TERMS >= 2) ldmx4(al, bb + S::SAl * TILE_B + mbase);
#pragma unroll
            for (int ni = 0; ni < 4; ++ni) {
                mma_f16(acc[mi * 4 + ni], ah, bh[ni]);
                if (TERMS >= 2) mma_f16(acc[mi * 4 + ni], al, bh[ni]);
                if (TERMS == 3) mma_f16(acc[mi * 4 + ni], ah, bl[ni]);
            }
        }
    }
}

// issue cp.async for one fp16 tile (2x16B chunks/thread)
__device__ __forceinline__ void issue_tile(uint32_t bb, int tile, const hf* base,
                                           int ld, int k0, int t) {
    int row = t >> 2, q = t & 3;
    cp16(bb + tile * TILE_B + row * 80 + q * 16, base + (size_t)row * ld + k0 + q * 8);
    row = (t + 256) >> 2; q = (t + 256) & 3;
    cp16(bb + tile * TILE_B + row * 80 + q * 16, base + (size_t)row * ld + k0 + q * 8);
}

// ---------------- flat K=128 helpers: interleaved [A_kt | B_kt] x 4, 81920 B -------
__device__ __forceinline__ void flat_load(uint32_t sb, const hf* A, int lda,
                                          const hf* B, int ldb, int t) {
#pragma unroll
    for (int kt = 0; kt < 4; ++kt) {
        issue_tile(sb + kt * 2 * TILE_B, 0, A, lda, kt * KT, t);
        issue_tile(sb + kt * 2 * TILE_B, 1, B, ldb, kt * KT, t);
    }
    cp_commit();
}
__device__ __forceinline__ void flat_compute(uint32_t sb, float acc[16][4],
                                             int a_off, int b_off, int wr, int wc) {
#pragma unroll
    for (int kt = 0; kt < 4; ++kt)
        compute_kt<1>(sb + kt * 2 * TILE_B, acc, a_off, b_off, wr, wc);
}
#define FLAT_SMEM (8 * TILE_B)   // 81920

// ---------------- streaming core (stage A: fp32 A, in-kernel cvt) ----------------
__device__ __forceinline__ void mm_a_core(const float* __restrict__ A, int lda,
                                          const hf* __restrict__ Bh, int ldb,
                                          int ktiles, float acc[16][4], float ascale) {
    using S = Slots<1>;
    extern __shared__ __align__(128) char dsm[];
    const int t = threadIdx.x, lane = t & 31, w = t >> 5;
    const int wr = w >> 2, wc = w & 3;
    const uint32_t sb = smem_u32(dsm);
    const int a_off = ((lane & 7) + ((lane >> 3) & 1) * 8) * 80 + ((lane >> 4) & 1) * 16;
    const int b_off = ((lane & 7) + ((lane >> 4) & 1) * 8) * 80 + ((lane >> 3) & 1) * 16;

#pragma unroll
    for (int i = 0; i < 16; ++i)
#pragma unroll
        for (int j = 0; j < 4; ++j) acc[i][j] = 0.0f;

    float4 av[4];
    issue_tile(sb, S::SBh, Bh, ldb, 0, t);
    cp_commit();
#pragma unroll
    for (int i = 0; i < 4; ++i) {
        const int idx = t + 256 * i, r = idx >> 3, c4 = (idx & 7) << 2;
        av[i] = *(const float4*)&A[(size_t)r * lda + c4];
    }
#pragma unroll
    for (int i = 0; i < 4; ++i) {
        const int idx = t + 256 * i, r = idx >> 3, c4 = (idx & 7) << 2;
        *(uint2*)(dsm + S::SAh * TILE_B + r * 80 + c4 * 2) = cvt_h4s(av[i], ascale);
    }

    int cur = 0;
    for (int kt = 0; kt < ktiles; ++kt) {
        const bool more = (kt + 1 < ktiles);
        if (more) {
#pragma unroll
            for (int i = 0; i < 4; ++i) {
                const int idx = t + 256 * i, r = idx >> 3, c4 = (idx & 7) << 2;
                av[i] = *(const float4*)&A[(size_t)r * lda + (kt + 1) * KT + c4];
            }
            issue_tile(sb + (cur ^ 1) * S::BUF, S::SBh, Bh, ldb, (kt + 1) * KT, t);
            cp_commit();
            cp_wait<1>();
        } else {
            cp_wait<0>();
        }
        __syncthreads();
        compute_kt<1>(sb + cur * S::BUF, acc, a_off, b_off, wr, wc);
        __syncthreads();
        if (more) {
#pragma unroll
            for (int i = 0; i < 4; ++i) {
                const int idx = t + 256 * i, r = idx >> 3, c4 = (idx & 7) << 2;
                *(uint2*)(dsm + (cur ^ 1) * S::BUF + S::SAh * TILE_B + r * 80 + c4 * 2) =
                    cvt_h4s(av[i], ascale);
            }
        }
        cur ^= 1;
    }
}

// ---------------- fused prep kernel ----------------
#define WT_B0  16
#define TWB_B0 1040
#define TBS_B0 1552
__global__ void __launch_bounds__(256) prep_kernel(const float* __restrict__ Aop,
                                                   const float* __restrict__ Bop,
                                                   const float* __restrict__ Dout,
                                                   const float* __restrict__ Din,
                                                   const float* __restrict__ product,
                                                   const float* __restrict__ wgt,
                                                   const float* __restrict__ wb,
                                                   const float* __restrict__ bases) {
    __shared__ float sm[5120];   // 20 KB
    const int bid = blockIdx.x;
    const int t = threadIdx.x;

    if (bid < WT_B0) {
        const int j = bid;
        float* Aj = sm;
        float* Bj = sm + 512;
        float* Qs = sm + 1024;
        for (int i = t; i < NR * 64; i += 256) {
            Aj[i] = Aop[j * (NR * 64) + i];
            Bj[i] = Bop[j * (NR * 64) + i];
        }
        __syncthreads();
#pragma unroll
        for (int s = 0; s < 16; ++s) {
            int idx = t + 256 * s;
            int m = idx >> 6, n = idx & 63;
            float q = 0.0f;
#pragma unroll
            for (int r = 0; r < NR; ++r) q += Aj[r * 64 + m] * Bj[r * 64 + n];
            Qs[idx] = q;
        }
        __syncthreads();
#pragma unroll 4
        for (int s = 0; s < 64; ++s) {
            int idx = t + 256 * s;        // 16384 = 128x128
            int k = idx >> 7, l = idx & 127;
            float h = Dout[j * 128 + k] * Din[j * 128 + l] * product[k * 128 + l];
            if (k < 64 && l < 64) h += Qs[k * 64 + l];
            g_Hk_h[k * (NJ * 128) + j * 128 + l] = __float2half_rn(h);
        }
    } else if (bid < TWB_B0) {
        int id = (bid - WT_B0) * 256 + t;   // 262144
        g_xhatT[id] = 0.0f;
        g_y[id]     = 0.0f;
        int ii = id & 127;
        int o  = (id >> 7) & 127;
        int j  = id >> 14;
        g_Wt_h[id] = __float2half_rn(wgt[(ii * 128 + o) * NJ + j] * WSCALE);
    } else if (bid < TBS_B0) {
        const int bt = bid - TWB_B0;        // 0..511
        const int xb = (bt >> 2) * 128;
        const int kb = (bt & 3) * 32;
        const int q  = t & 7;
#pragma unroll
        for (int p = 0; p < 4; ++p) {
            const int xr = p * 32 + (t >> 3);
            float4 v = *(const float4*)&wb[(size_t)(xb + xr) * 128 + kb + q * 4];
            sm[(q * 4 + 0) * 129 + xr] = v.x;
            sm[(q * 4 + 1) * 129 + xr] = v.y;
            sm[(q * 4 + 2) * 129 + xr] = v.z;
            sm[(q * 4 + 3) * 129 + xr] = v.w;
        }
        __syncthreads();
        const int kr = t >> 3;
        const int xq = (t & 7) * 16;
        const float* row = &sm[kr * 129 + xq];
        uint32_t pk[8];
#pragma unroll
        for (int m = 0; m < 8; ++m) {
            __half2 h = __floats2half2_rn(row[2 * m], row[2 * m + 1]);
            pk[m] = *(uint32_t*)&h;
        }
        hf* dst = &g_wbT_h[(size_t)(kb + kr) * NPTS + xb + xq];
        *(uint4*)dst       = make_uint4(pk[0], pk[1], pk[2], pk[3]);
        *(uint4*)(dst + 8) = make_uint4(pk[4], pk[5], pk[6], pk[7]);
    } else {
        const int bt = bid - TBS_B0;        // 0..511
#pragma unroll
        for (int s = 0; s < 4; ++s) {
            int i4 = bt * 256 + t + s * 131072;
            float4 v = ((const float4*)bases)[i4];
            *(uint2*)&g_bs_h[(size_t)i4 * 4] = cvt_h4(v);
        }
    }
}

// xhatT fp32 -> fp16 hi
__global__ void __launch_bounds__(256) cvt0_kernel() {
    int i4 = blockIdx.x * 256 + threadIdx.x;
    float4 v = ((const float4*)g_xhatT)[i4];
    *(uint2*)&g_xhT_h[(size_t)i4 * 4] = cvt_h4(v);
}

// y fp32 (scaled) -> fp16 descaled
__global__ void __launch_bounds__(256) cvty_kernel() {
    int i4 = blockIdx.x * 256 + threadIdx.x;
    float4 v = ((const float4*)g_y)[i4];
    *(uint2*)&g_y_h[(size_t)i4 * 4] = cvt_h4s(v, WINV);
}

// ---------------- GEMM stage kernels ----------------
// stage A: xhatT[b][l][i] += x[(b,i),:] @ wbT  (16 b-blocks x 16 K-splits, 1-term)
__global__ void __launch_bounds__(256) k_mm_a(const float* __restrict__ x) {
    const int b  = blockIdx.x;
    const int ks = blockIdx.y;
    float acc[16][4];
    mm_a_core(x + (size_t)(b * 128) * NPTS + ks * 1024, NPTS,
              g_wbT_h + ks * 1024, NPTS, 32, acc, 1.0f);
    const int lane = threadIdx.x & 31, w = threadIdx.x >> 5;
    const int wr = w >> 2, wc = w & 3;
    float* dst = g_xhatT + (size_t)b * 16384;
#pragma unroll
    for (int mi = 0; mi < 4; ++mi)
#pragma unroll
        for (int ni = 0; ni < 4; ++ni) {
            const int row = wr * 64 + mi * 16 + (lane >> 2);   // i
            const int col = wc * 32 + ni * 8 + (lane & 3) * 2; // l
            const float* a = acc[mi * 4 + ni];
            atomicAdd(&dst[(col + 0) * 128 + row],     a[0]);
            atomicAdd(&dst[(col + 1) * 128 + row],     a[1]);
            atomicAdd(&dst[(col + 0) * 128 + row + 8], a[2]);
            atomicAdd(&dst[(col + 1) * 128 + row + 8], a[3]);
        }
}

// fused stage ZY (flat): all tiles resident, 3 syncs total.
// smem: interleaved [A_kt | B_kt] x 4 = 81920 B -> 2 CTAs/SM.
// Phase 1: A=Wt_j, B=xhat_b -> ztile acc. Phase 2: A-slots <- ztile (STS),
// B-slots <- Hk_j (cp.async), then GEMM2 -> atomic y.
__global__ void __launch_bounds__(256, 2) k_mm_zy() {
    extern __shared__ __align__(128) char dsm[];
    const int b = blockIdx.x >> 4, j = blockIdx.x & 15;
    const int t = threadIdx.x, lane = t & 31, w = t >> 5;
    const int wr = w >> 2, wc = w & 3;
    const uint32_t sb = smem_u32(dsm);
    const int a_off = ((lane & 7) + ((lane >> 3) & 1) * 8) * 80 + ((lane >> 4) & 1) * 16;
    const int b_off = ((lane & 7) + ((lane >> 4) & 1) * 8) * 80 + ((lane >> 3) & 1) * 16;

    float acc[16][4];
#pragma unroll
    for (int i = 0; i < 16; ++i)
#pragma unroll
        for (int q = 0; q < 4; ++q) acc[i][q] = 0.0f;

    // ---- Phase 1: GEMM1 = Wt_h[j] @ xhat_h[b] ----
    flat_load(sb, g_Wt_h + (size_t)j * 16384, 128,
              g_xhT_h + (size_t)b * 16384, 128, t);
    cp_wait<0>();
    __syncthreads();
    flat_compute(sb, acc, a_off, b_off, wr, wc);
    __syncthreads();   // all warps done reading W/X tiles

    // ---- Phase 2 staging: ztile -> A-slots; Hk -> B-slots ----
#pragma unroll
    for (int mi = 0; mi < 4; ++mi)
#pragma unroll
        for (int ni = 0; ni < 4; ++ni) {
            const int row = wr * 64 + mi * 16 + (lane >> 2);      // o
            const int tc  = (ni * 8 + (lane & 3) * 2) * 2;        // byte col within tile
            const uint32_t hoff = wc * 2 * TILE_B + row * 80 + tc;   // A-slot of tile wc
            const float* a = acc[mi * 4 + ni];
            __half2 h0 = __floats2half2_rn(a[0], a[1]);
            __half2 h1 = __floats2half2_rn(a[2], a[3]);
            *(uint32_t*)(dsm + hoff)          = *(uint32_t*)&h0;
            *(uint32_t*)(dsm + hoff + 8 * 80) = *(uint32_t*)&h1;
        }
    const hf* Bh = g_Hk_h + j * 128;     // rows k, stride 2048
#pragma unroll
    for (int kt = 0; kt < 4; ++kt)
        issue_tile(sb + kt * 2 * TILE_B, 1, Bh, 2048, kt * KT, t);
    cp_commit();

#pragma unroll
    for (int i = 0; i < 16; ++i)
#pragma unroll
        for (int q = 0; q < 4; ++q) acc[i][q] = 0.0f;

    cp_wait<0>();
    __syncthreads();
    flat_compute(sb, acc, a_off, b_off, wr, wc);

    // ---- epilogue: atomic accumulate into g_y ----
#pragma unroll
    for (int mi = 0; mi < 4; ++mi)
#pragma unroll
        for (int ni = 0; ni < 4; ++ni) {
            const int row = b * 128 + wr * 64 + mi * 16 + (lane >> 2);  // (b,o)
            const int col = wc * 32 + ni * 8 + (lane & 3) * 2;          // k
            const float* a = acc[mi * 4 + ni];
            atomicAdd(&g_y[(size_t)row * 128 + col],           a[0]);
            atomicAdd(&g_y[(size_t)row * 128 + col + 1],       a[1]);
            atomicAdd(&g_y[(size_t)(row + 8) * 128 + col],     a[2]);
            atomicAdd(&g_y[(size_t)(row + 8) * 128 + col + 1], a[3]);
        }
}

// stage D (flat): out = y_h @ bases_h^T, all tiles resident, 1 sync
__global__ void __launch_bounds__(256, 2) k_mm_d(float* __restrict__ out) {
    extern __shared__ __align__(128) char dsm[];
    const int row0 = blockIdx.x * 128;
    const int x0   = blockIdx.y * 128;
    const int t = threadIdx.x, lane = t & 31, w = t >> 5;
    const int wr = w >> 2, wc = w & 3;
    const uint32_t sb = smem_u32(dsm);
    const int a_off = ((lane & 7) + ((lane >> 3) & 1) * 8) * 80 + ((lane >> 4) & 1) * 16;
    const int b_off = ((lane & 7) + ((lane >> 4) & 1) * 8) * 80 + ((lane >> 3) & 1) * 16;

    float acc[16][4];
#pragma unroll
    for (int i = 0; i < 16; ++i)
#pragma unroll
        for (int q = 0; q < 4; ++q) acc[i][q] = 0.0f;

    flat_load(sb, g_y_h + (size_t)row0 * 128, 128,
              g_bs_h + (size_t)x0 * 128, 128, t);
    cp_wait<0>();
    __syncthreads();
    flat_compute(sb, acc, a_off, b_off, wr, wc);

#pragma unroll
    for (int mi = 0; mi < 4; ++mi)
#pragma unroll
        for (int ni = 0; ni < 4; ++ni) {
            const int row = row0 + wr * 64 + mi * 16 + (lane >> 2);
            const int col = x0 + wc * 32 + ni * 8 + (lane & 3) * 2;
            const float* a = acc[mi * 4 + ni];
            *(float2*)&out[(size_t)row * NPTS + col]       = make_float2(a[0], a[1]);
            *(float2*)&out[(size_t)(row + 8) * NPTS + col] = make_float2(a[2], a[3]);
        }
}

// ---------------- launch ----------------
extern "C" void kernel_launch(void* const* d_in, const int* in_sizes, int n_in,
                              void* d_out, int out_size) {
    const float* x       = (const float*)d_in[0];
    const float* bases   = (const float*)d_in[1];
    const float* wbases  = (const float*)d_in[2];
    const float* product = (const float*)d_in[3];
    const float* Dout    = (const float*)d_in[4];
    const float* Din     = (const float*)d_in[5];
    const float* Aop     = (const float*)d_in[6];
    const float* Bop     = (const float*)d_in[7];
    const float* weights = (const float*)d_in[8];
    float* out = (float*)d_out;

    const int SM_1 = 2 * Slots<1>::BUF;   // 40960
    cudaFuncSetAttribute(k_mm_a,  cudaFuncAttributeMaxDynamicSharedMemorySize, SM_1);
    cudaFuncSetAttribute(k_mm_zy, cudaFuncAttributeMaxDynamicSharedMemorySize, FLAT_SMEM);
    cudaFuncSetAttribute(k_mm_d,  cudaFuncAttributeMaxDynamicSharedMemorySize, FLAT_SMEM);

    prep_kernel<<<2064, 256>>>(Aop, Bop, Dout, Din, product, weights, wbases, bases);
    k_mm_a<<<dim3(16, 16), 256, SM_1>>>(x);
    cvt0_kernel<<<256, 256>>>();
    k_mm_zy<<<NB * NJ, 256, FLAT_SMEM>>>();
    cvty_kernel<<<256, 256>>>();
    k_mm_d<<<dim3(16, 128), 256, FLAT_SMEM>>>(out);
}